// round 15
// baseline (speedup 1.0000x reference)
#include <cuda_runtime.h>
#include <cuda_fp16.h>
#include <math.h>
#include <stdint.h>

#define DEPTHN 12
#define BATCH 128
#define NTOK 197
#define NSP 196
#define CDIM 384
#define NHEAD 6
#define HDIM 64
#define MROWS (BATCH*NTOK)      /* 25216 */
#define FFDIM 1536
#define QKVDIM 1152

/* per-layer packed half-weight layout */
#define W_QKV_OFF 0
#define W_PROJ_OFF 442368
#define W_FC1_OFF 589824
#define W_FC2_OFF 1179648
#define LW 1769472

/* ---------------- scratch (device globals; zero-initialized) ------------- */
__device__ float  g_x   [MROWS*CDIM];
__device__ __half g_h16 [MROWS*CDIM];
__device__ __half g_qkv16[MROWS*QKVDIM];
__device__ __half g_ao16[MROWS*CDIM];
__device__ __half g_ffn16[(long long)MROWS*FFDIM];
__device__ __half g_wh  [(long long)DEPTHN*LW];
__device__ float  g_pol [BATCH*NTOK];
__device__ float  g_ph  [BATCH*NSP*NHEAD*HDIM];
__device__ float  g_glob[BATCH*NHEAD*32];
__device__ float  g_den [BATCH];

__device__ __forceinline__ float gelu_f(float x) {
    return 0.5f * x * (1.0f + erff(x * 0.70710678118654752440f));
}

__device__ __forceinline__ uint32_t smem_u32(const void* p) {
    uint32_t a;
    asm("{ .reg .u64 t; cvta.to.shared.u64 t, %1; cvt.u32.u64 %0, t; }" : "=r"(a) : "l"(p));
    return a;
}

__device__ __forceinline__ uint32_t pack_h2(float lo, float hi) {
    uint32_t r;
    asm("cvt.rn.f16x2.f32 %0, %1, %2;" : "=r"(r) : "f"(hi), "f"(lo));
    return r;
}

__device__ __forceinline__ void cp_async16(uint32_t saddr, const void* g) {
    asm volatile("cp.async.cg.shared.global [%0], [%1], 16;" :: "r"(saddr), "l"(g));
}
#define CP_COMMIT() asm volatile("cp.async.commit_group;" ::: "memory")
#define CP_WAIT(n)  asm volatile("cp.async.wait_group %0;" :: "n"(n) : "memory")

__device__ __forceinline__ void ldsm_x4(uint32_t& r0, uint32_t& r1,
                                        uint32_t& r2, uint32_t& r3, uint32_t a) {
    asm volatile("ldmatrix.sync.aligned.m8n8.x4.shared.b16 {%0,%1,%2,%3}, [%4];"
                 : "=r"(r0), "=r"(r1), "=r"(r2), "=r"(r3) : "r"(a));
}
__device__ __forceinline__ void ldsm_x2(uint32_t& r0, uint32_t& r1, uint32_t a) {
    asm volatile("ldmatrix.sync.aligned.m8n8.x2.shared.b16 {%0,%1}, [%2];"
                 : "=r"(r0), "=r"(r1) : "r"(a));
}

__device__ __forceinline__ void mma_f16(
    float& d0, float& d1, float& d2, float& d3,
    uint32_t a0, uint32_t a1, uint32_t a2, uint32_t a3,
    uint32_t b0, uint32_t b1)
{
    asm volatile(
        "mma.sync.aligned.m16n8k16.row.col.f32.f16.f16.f32 "
        "{%0,%1,%2,%3}, {%4,%5,%6,%7}, {%8,%9}, {%0,%1,%2,%3};"
        : "+f"(d0), "+f"(d1), "+f"(d2), "+f"(d3)
        : "r"(a0), "r"(a1), "r"(a2), "r"(a3), "r"(b0), "r"(b1));
}

/* fp16-accumulator variant: D,C are 2 f16x2 regs */
__device__ __forceinline__ void mma_f16acc(
    uint32_t& d0, uint32_t& d1,
    uint32_t a0, uint32_t a1, uint32_t a2, uint32_t a3,
    uint32_t b0, uint32_t b1)
{
    asm volatile(
        "mma.sync.aligned.m16n8k16.row.col.f16.f16.f16.f16 "
        "{%0,%1}, {%2,%3,%4,%5}, {%6,%7}, {%0,%1};"
        : "+r"(d0), "+r"(d1)
        : "r"(a0), "r"(a1), "r"(a2), "r"(a3), "r"(b0), "r"(b1));
}

/* ---------------- weight fp32 -> fp16 (2D grid, half2 vectorized) -------- */
__global__ void cvtw_k(const float* __restrict__ src, __half* __restrict__ dstbase,
                       int perL, int off)
{
    int l = blockIdx.y;
    long long i = ((long long)blockIdx.x * blockDim.x + threadIdx.x) * 2;
    if (i < perL) {
        float2 v = *(const float2*)(src + (long long)l * perL + i);
        *(__half2*)(dstbase + (long long)l * LW + off + i) = __floats2half2_rn(v.x, v.y);
    }
}

/* ================= dense fp16 HMMA GEMM (fp16-acc probe) =================
 * C[m,n] = sum_k A[m,k]*B[n,k] + bias[n]   (EPI: 0 none, 1 gelu, 2 +R)
 * 256 threads, 8 warps (2M x 4N), warp 64x32; ldmatrix; 2-stage cp.async.
 * Inner k-tile (K=64, 4 mma) accumulates in fp16; per-tile fixup to fp32.
 */
#define DENSE_SMEM 73728

template<int EPI, bool OUTH>
__global__ void __launch_bounds__(256)
hgemm_k(const __half* __restrict__ A, const __half* __restrict__ B,
        const float* __restrict__ bias, const float* __restrict__ R,
        void* __restrict__ Cv, int K, int lda, int ldb, int ldc)
{
    extern __shared__ __half hsm[];
    __half* As = hsm;              /* [2][128*72] */
    __half* Bs = hsm + 18432;
    const uint32_t asb = smem_u32(As), bsb = smem_u32(Bs);

    const int tid = threadIdx.x, wid = tid >> 5, lane = tid & 31;
    const int lane4 = lane >> 2, lanek = lane & 3;
    const int warpM = wid & 1, warpN = wid >> 1;
    const int m0 = blockIdx.y * 128, n0 = blockIdx.x * 128;

    const int mat = lane >> 3;
    const int arow = (lane & 7) + (mat & 1) * 8;
    const int acol = (mat >> 1) * 8;
    const int brow = lane & 7;
    const int bcol = ((lane >> 3) & 1) * 8;

    float acc[4][4][4];
    #pragma unroll
    for (int i = 0; i < 4; i++)
        #pragma unroll
        for (int j = 0; j < 4; j++)
            #pragma unroll
            for (int r = 0; r < 4; r++) acc[i][j][r] = 0.f;

#define HISSUE(t_, s_) do {                                                     \
    int k0_ = (t_) * 64;                                                        \
    _Pragma("unroll")                                                           \
    for (int i_ = 0; i_ < 4; i_++) {                                            \
        int idx_ = tid + 256 * i_;                                              \
        int row_ = idx_ >> 3, ch_ = idx_ & 7;                                   \
        uint32_t so_ = (uint32_t)(((s_) * 9216 + row_ * 72 + ch_ * 8) * 2);     \
        cp_async16(asb + so_, A + (size_t)(m0 + row_) * lda + k0_ + ch_ * 8);   \
        cp_async16(bsb + so_, B + (size_t)(n0 + row_) * ldb + k0_ + ch_ * 8);   \
    }                                                                           \
    CP_COMMIT();                                                                \
} while (0)

    const int T = K >> 6;
    HISSUE(0, 0);

    for (int t = 0; t < T; t++) {
        int p = t & 1;
        if (t + 1 < T) { HISSUE(t + 1, p ^ 1); CP_WAIT(1); }
        else           { CP_WAIT(0); }
        __syncthreads();

        uint32_t aAddr[4], bAddr[4];
        #pragma unroll
        for (int mf = 0; mf < 4; mf++)
            aAddr[mf] = asb + (uint32_t)((p * 9216 + (warpM * 64 + mf * 16 + arow) * 72 + acol) * 2);
        #pragma unroll
        for (int nf = 0; nf < 4; nf++)
            bAddr[nf] = bsb + (uint32_t)((p * 9216 + (warpN * 32 + nf * 8 + brow) * 72 + bcol) * 2);

        uint32_t facc[4][4][2];
        #pragma unroll
        for (int mf = 0; mf < 4; mf++)
            #pragma unroll
            for (int nf = 0; nf < 4; nf++) { facc[mf][nf][0] = 0u; facc[mf][nf][1] = 0u; }

        #pragma unroll
        for (int ks = 0; ks < 4; ks++) {
            uint32_t a[4][4], b[4][2];
            #pragma unroll
            for (int mf = 0; mf < 4; mf++)
                ldsm_x4(a[mf][0], a[mf][1], a[mf][2], a[mf][3], aAddr[mf] + ks * 32);
            #pragma unroll
            for (int nf = 0; nf < 4; nf++)
                ldsm_x2(b[nf][0], b[nf][1], bAddr[nf] + ks * 32);
            #pragma unroll
            for (int mf = 0; mf < 4; mf++)
                #pragma unroll
                for (int nf = 0; nf < 4; nf++)
                    mma_f16acc(facc[mf][nf][0], facc[mf][nf][1],
                               a[mf][0], a[mf][1], a[mf][2], a[mf][3],
                               b[nf][0], b[nf][1]);
        }

        /* per-tile fp32 fixup */
        #pragma unroll
        for (int mf = 0; mf < 4; mf++)
            #pragma unroll
            for (int nf = 0; nf < 4; nf++) {
                float2 lo = __half22float2(*(__half2*)&facc[mf][nf][0]);
                float2 hi = __half22float2(*(__half2*)&facc[mf][nf][1]);
                acc[mf][nf][0] += lo.x; acc[mf][nf][1] += lo.y;
                acc[mf][nf][2] += hi.x; acc[mf][nf][3] += hi.y;
            }

        if (t + 1 < T) __syncthreads();
    }
#undef HISSUE

    /* epilogue */
    #pragma unroll
    for (int mf = 0; mf < 4; mf++) {
        int m = m0 + warpM * 64 + mf * 16 + lane4;
        #pragma unroll
        for (int nf = 0; nf < 4; nf++) {
            int n = n0 + warpN * 32 + nf * 8 + lanek * 2;
            float bz0 = bias ? __ldg(bias + n)     : 0.f;
            float bz1 = bias ? __ldg(bias + n + 1) : 0.f;
            size_t gi0 = (size_t)m * ldc + n;
            size_t gi1 = (size_t)(m + 8) * ldc + n;
            float v0 = acc[mf][nf][0] + bz0;
            float v1 = acc[mf][nf][1] + bz1;
            float v2 = acc[mf][nf][2] + bz0;
            float v3 = acc[mf][nf][3] + bz1;
            if (EPI == 1) {
                v0 = gelu_f(v0); v1 = gelu_f(v1);
                v2 = gelu_f(v2); v3 = gelu_f(v3);
            } else if (EPI == 2) {
                v0 += R[gi0]; v1 += R[gi0 + 1];
                v2 += R[gi1]; v3 += R[gi1 + 1];
            }
            if (OUTH) {
                __half* C = (__half*)Cv;
                *(__half2*)(C + gi0) = __floats2half2_rn(v0, v1);
                *(__half2*)(C + gi1) = __floats2half2_rn(v2, v3);
            } else {
                float* C = (float*)Cv;
                *(float2*)(C + gi0) = make_float2(v0, v1);
                *(float2*)(C + gi1) = make_float2(v2, v3);
            }
        }
    }
}

/* ================= fused attention: S=QK^T -> softmax -> O=P@V =========== */
#define FUSED_SMEM 90112

__global__ void __launch_bounds__(256)
attn_fused_k(const __half* __restrict__ qkv, const float* __restrict__ pol,
             __half* __restrict__ ao)
{
    extern __shared__ __half ssm[];
    __half* Qs = ssm;                       /* [128][72]  */
    __half* Ks = ssm + 9216;                /* [256][72]  */
    __half* Vs = ssm + 27648;               /* [64][264]  */
    float* pol_s = (float*)(ssm + 44544);

    const int tid = threadIdx.x, wid = tid >> 5, lane = tid & 31;
    const int bh = blockIdx.y, b = bh / NHEAD, h = bh % NHEAD;
    const int m0 = blockIdx.x * 128;

    const int mat = lane >> 3;
    const int arow = (lane & 7) + (mat & 1) * 8;
    const int acol = (mat >> 1) * 8;
    const int brow = (lane & 7) + ((lane >> 4) << 3);
    const int bcol = ((lane >> 3) & 1) * 8;
    const int vrow = lane & 7;
    const int vcol = ((lane >> 3) & 1) * 8;

    const __half* qb = qkv + (size_t)b * NTOK * QKVDIM + h * HDIM;
    const __half* kb = qb + CDIM;
    const __half* vb = qb + 2 * CDIM;

    for (int i = tid; i < NTOK; i += 256) pol_s[i] = pol[b * NTOK + i];

    const uint4 zero4 = make_uint4(0, 0, 0, 0);
    #pragma unroll
    for (int p = 0; p < 2; p++) {
        int row = (tid >> 2) + p * 64;
        int col = (tid & 3) * 16;
        uint4 v0 = zero4, v1 = zero4;
        if (m0 + row < NTOK) {
            const __half* s = qb + (size_t)(m0 + row) * QKVDIM + col;
            v0 = *(const uint4*)s; v1 = *(const uint4*)(s + 8);
        }
        *(uint4*)&Qs[row * 72 + col]     = v0;
        *(uint4*)&Qs[row * 72 + col + 8] = v1;
    }
    #pragma unroll
    for (int p = 0; p < 4; p++) {
        int row = (tid >> 2) + p * 64;
        int col = (tid & 3) * 16;
        uint4 v0 = zero4, v1 = zero4;
        if (row < NTOK) {
            const __half* s = kb + (size_t)row * QKVDIM + col;
            v0 = *(const uint4*)s; v1 = *(const uint4*)(s + 8);
        }
        *(uint4*)&Ks[row * 72 + col]     = v0;
        *(uint4*)&Ks[row * 72 + col + 8] = v1;
    }
    {
        int n = tid & 63, k4 = tid >> 6;
        #pragma unroll
        for (int i = 0; i < 64; i++) {
            int k = k4 + 4 * i;
            __half v = (k < NTOK) ? vb[(size_t)k * QKVDIM + n] : __half(0.f);
            Vs[n * 264 + k] = v;
        }
    }
    __syncthreads();

    /* ---- S = Q @ K^T ---- */
    float acc[32][4];
    #pragma unroll
    for (int j = 0; j < 32; j++)
        #pragma unroll
        for (int r = 0; r < 4; r++) acc[j][r] = 0.f;

    const uint32_t qsb = smem_u32(Qs), ksb = smem_u32(Ks), vsb = smem_u32(Vs);
    const uint32_t aBase = qsb + (uint32_t)(((wid * 16 + arow) * 72 + acol) * 2);
    const uint32_t bBase = ksb + (uint32_t)((brow * 72 + bcol) * 2);

    #pragma unroll
    for (int ks = 0; ks < 4; ks++) {
        uint32_t a0, a1, a2, a3;
        ldsm_x4(a0, a1, a2, a3, aBase + ks * 32);
        #pragma unroll
        for (int ng = 0; ng < 16; ng++) {
            uint32_t b0, b1, b2, b3;
            ldsm_x4(b0, b1, b2, b3, bBase + (uint32_t)(ng * 16 * 72 * 2) + ks * 32);
            mma_f16(acc[ng*2][0], acc[ng*2][1], acc[ng*2][2], acc[ng*2][3],
                    a0, a1, a2, a3, b0, b1);
            mma_f16(acc[ng*2+1][0], acc[ng*2+1][1], acc[ng*2+1][2], acc[ng*2+1][3],
                    a0, a1, a2, a3, b2, b3);
        }
    }

    /* ---- in-register policy softmax ---- */
    const int rr = lane >> 2, t = lane & 3;
    const int gm1 = m0 + wid * 16 + rr;
    const int gm2 = gm1 + 8;

    #pragma unroll
    for (int j = 0; j < 32; j++) {
        acc[j][0] *= 0.125f; acc[j][1] *= 0.125f;
        acc[j][2] *= 0.125f; acc[j][3] *= 0.125f;
    }

    float mx1 = -1e30f, mx2 = -1e30f;
    #pragma unroll
    for (int j = 0; j < 32; j++) {
        int col = j * 8 + t * 2;
        if (col < NTOK)     { mx1 = fmaxf(mx1, acc[j][0]); mx2 = fmaxf(mx2, acc[j][2]); }
        if (col + 1 < NTOK) { mx1 = fmaxf(mx1, acc[j][1]); mx2 = fmaxf(mx2, acc[j][3]); }
    }
    mx1 = fmaxf(mx1, __shfl_xor_sync(0xffffffffu, mx1, 1));
    mx1 = fmaxf(mx1, __shfl_xor_sync(0xffffffffu, mx1, 2));
    mx2 = fmaxf(mx2, __shfl_xor_sync(0xffffffffu, mx2, 1));
    mx2 = fmaxf(mx2, __shfl_xor_sync(0xffffffffu, mx2, 2));

    float sum1 = 0.f, sum2 = 0.f;
    #pragma unroll
    for (int j = 0; j < 32; j++) {
        int col = j * 8 + t * 2;
        if (col < NTOK) {
            float ap = pol_s[col];
            float a1v = (col == gm1) ? 1.0f : ap;
            float a2v = (col == gm2) ? 1.0f : ap;
            float e1 = __expf(acc[j][0] - mx1) * a1v; acc[j][0] = e1; sum1 += e1;
            float e2 = __expf(acc[j][2] - mx2) * a2v; acc[j][2] = e2; sum2 += e2;
        } else { acc[j][0] = 0.f; acc[j][2] = 0.f; }
        if (col + 1 < NTOK) {
            float ap = pol_s[col + 1];
            float a1v = (col + 1 == gm1) ? 1.0f : ap;
            float a2v = (col + 1 == gm2) ? 1.0f : ap;
            float e1 = __expf(acc[j][1] - mx1) * a1v; acc[j][1] = e1; sum1 += e1;
            float e2 = __expf(acc[j][3] - mx2) * a2v; acc[j][3] = e2; sum2 += e2;
        } else { acc[j][1] = 0.f; acc[j][3] = 0.f; }
    }
    sum1 += __shfl_xor_sync(0xffffffffu, sum1, 1);
    sum1 += __shfl_xor_sync(0xffffffffu, sum1, 2);
    sum2 += __shfl_xor_sync(0xffffffffu, sum2, 1);
    sum2 += __shfl_xor_sync(0xffffffffu, sum2, 2);
    float inv1 = 1.0f / sum1, inv2 = 1.0f / sum2;

    /* ---- pack P: C-fragment layout -> A-fragments ---- */
    uint32_t pa[16][4];
    #pragma unroll
    for (int g = 0; g < 16; g++) {
        pa[g][0] = pack_h2(acc[2*g][0]   * inv1, acc[2*g][1]   * inv1);
        pa[g][1] = pack_h2(acc[2*g][2]   * inv2, acc[2*g][3]   * inv2);
        pa[g][2] = pack_h2(acc[2*g+1][0] * inv1, acc[2*g+1][1] * inv1);
        pa[g][3] = pack_h2(acc[2*g+1][2] * inv2, acc[2*g+1][3] * inv2);
    }

    /* ---- O = P @ V ---- */
    float oacc[8][4];
    #pragma unroll
    for (int nf = 0; nf < 8; nf++)
        #pragma unroll
        for (int r = 0; r < 4; r++) oacc[nf][r] = 0.f;

    uint32_t vAddr[8];
    #pragma unroll
    for (int nf = 0; nf < 8; nf++)
        vAddr[nf] = vsb + (uint32_t)(((nf * 8 + vrow) * 264 + vcol) * 2);

    #pragma unroll
    for (int g = 0; g < 16; g++) {
        #pragma unroll
        for (int nf = 0; nf < 8; nf++) {
            uint32_t b0, b1;
            ldsm_x2(b0, b1, vAddr[nf] + g * 32);
            mma_f16(oacc[nf][0], oacc[nf][1], oacc[nf][2], oacc[nf][3],
                    pa[g][0], pa[g][1], pa[g][2], pa[g][3], b0, b1);
        }
    }

    /* ---- write O ---- */
    #pragma unroll
    for (int nf = 0; nf < 8; nf++) {
        int n = nf * 8 + t * 2;
        if (gm1 < NTOK)
            *(__half2*)(ao + (size_t)(b * NTOK + gm1) * CDIM + h * HDIM + n) =
                __floats2half2_rn(oacc[nf][0], oacc[nf][1]);
        if (gm2 < NTOK)
            *(__half2*)(ao + (size_t)(b * NTOK + gm2) * CDIM + h * HDIM + n) =
                __floats2half2_rn(oacc[nf][2], oacc[nf][3]);
    }
}

/* ---------------- block reductions --------------------------------------- */
__device__ __forceinline__ float blockReduceSum(float v, float* sh) {
    int tid = threadIdx.x, lane = tid & 31, w = tid >> 5;
    #pragma unroll
    for (int o = 16; o; o >>= 1) v += __shfl_xor_sync(0xffffffffu, v, o);
    if (lane == 0) sh[w] = v;
    __syncthreads();
    int nw = (blockDim.x + 31) >> 5;
    v = (tid < nw) ? sh[tid] : 0.f;
    if (w == 0) {
        #pragma unroll
        for (int o = 16; o; o >>= 1) v += __shfl_xor_sync(0xffffffffu, v, o);
        if (lane == 0) sh[0] = v;
    }
    __syncthreads();
    float r = sh[0];
    __syncthreads();
    return r;
}

/* ---------------- LayerNorm: warp-per-row, float4 I/O -------------------- */
__global__ void __launch_bounds__(256)
ln_k(const float* __restrict__ x, const float* __restrict__ w,
     const float* __restrict__ bb, __half* __restrict__ out, float eps)
{
    const int wid = threadIdx.x >> 5, lane = threadIdx.x & 31;
    const long long row = (long long)blockIdx.x * 8 + wid;
    const float4* xr = (const float4*)(x + row * CDIM);

    float4 v0 = xr[lane], v1 = xr[lane + 32], v2 = xr[lane + 64];
    float s = v0.x + v0.y + v0.z + v0.w
            + v1.x + v1.y + v1.z + v1.w
            + v2.x + v2.y + v2.z + v2.w;
    #pragma unroll
    for (int o = 16; o; o >>= 1) s += __shfl_xor_sync(0xffffffffu, s, o);
    float m = s * (1.f / 384.f);

    float q = (v0.x-m)*(v0.x-m) + (v0.y-m)*(v0.y-m) + (v0.z-m)*(v0.z-m) + (v0.w-m)*(v0.w-m)
            + (v1.x-m)*(v1.x-m) + (v1.y-m)*(v1.y-m) + (v1.z-m)*(v1.z-m) + (v1.w-m)*(v1.w-m)
            + (v2.x-m)*(v2.x-m) + (v2.y-m)*(v2.y-m) + (v2.z-m)*(v2.z-m) + (v2.w-m)*(v2.w-m);
    #pragma unroll
    for (int o = 16; o; o >>= 1) q += __shfl_xor_sync(0xffffffffu, q, o);
    float rs = rsqrtf(q * (1.f / 384.f) + eps);

    const float4* wv = (const float4*)w;
    const float4* bv = (const float4*)bb;
    __half* orow = out + row * CDIM;

    #pragma unroll
    for (int p = 0; p < 3; p++) {
        float4 vv = (p == 0) ? v0 : (p == 1) ? v1 : v2;
        float4 ww = wv[lane + p * 32];
        float4 bbv = bv[lane + p * 32];
        uint32_t lo = pack_h2((vv.x - m) * rs * ww.x + bbv.x,
                              (vv.y - m) * rs * ww.y + bbv.y);
        uint32_t hi = pack_h2((vv.z - m) * rs * ww.z + bbv.z,
                              (vv.w - m) * rs * ww.w + bbv.w);
        uint2 o2 = make_uint2(lo, hi);
        *(uint2*)(orow + (lane + p * 32) * 4) = o2;
    }
}

/* ---------------- tiled transpose init / final --------------------------- */
__global__ void init_tp_k(const float* __restrict__ xin, float* __restrict__ x)
{
    __shared__ float t[32][33];
    int b = blockIdx.z;
    int hw0 = blockIdx.x * 32, c0 = blockIdx.y * 32;
    int tx = threadIdx.x, ty = threadIdx.y;
    #pragma unroll
    for (int i = 0; i < 32; i += 8) {
        int c = c0 + ty + i, hw = hw0 + tx;
        if (hw < NSP)
            t[ty + i][tx] = xin[((size_t)b * CDIM + c) * NSP + hw];
    }
    __syncthreads();
    #pragma unroll
    for (int i = 0; i < 32; i += 8) {
        int hw = hw0 + ty + i, c = c0 + tx;
        if (hw < NSP)
            x[((size_t)b * NTOK + 1 + hw) * CDIM + c] = t[tx][ty + i];
    }
}

__global__ void init_aux_k(const float* __restrict__ cls, const float* __restrict__ polin,
                           float* __restrict__ x, float* __restrict__ pol)
{
    int idx = blockIdx.x * blockDim.x + threadIdx.x;
    if (idx < BATCH * CDIM) {
        int b = idx / CDIM, c = idx % CDIM;
        x[(size_t)b * NTOK * CDIM + c] = cls[idx];
    }
    if (idx < BATCH * NTOK) pol[idx] = polin[idx];
}

__global__ void final_tp_k(const float* __restrict__ x, float* __restrict__ out)
{
    __shared__ float t[32][33];
    int b = blockIdx.z;
    int hw0 = blockIdx.x * 32, c0 = blockIdx.y * 32;
    int tx = threadIdx.x, ty = threadIdx.y;
    #pragma unroll
    for (int i = 0; i < 32; i += 8) {
        int hw = hw0 + ty + i, c = c0 + tx;
        if (hw < NSP)
            t[ty + i][tx] = x[((size_t)b * NTOK + 1 + hw) * CDIM + c];
    }
    __syncthreads();
    #pragma unroll
    for (int i = 0; i < 32; i += 8) {
        int c = c0 + ty + i, hw = hw0 + tx;
        if (hw < NSP)
            out[((size_t)b * CDIM + c) * NSP + hw] = t[tx][ty + i];
    }
}

__global__ void final_aux_k(const float* __restrict__ x, float* __restrict__ out)
{
    int idx = blockIdx.x * blockDim.x + threadIdx.x;
    if (idx < BATCH * CDIM) {
        int b = idx / CDIM, c = idx % CDIM;
        out[(size_t)BATCH * CDIM * NSP + idx] = x[(size_t)b * NTOK * CDIM + c];
    }
}

/* ---------------- predictor --------------------------------------------- */
__global__ void den_k(const float* __restrict__ pol, float* __restrict__ den)
{
    __shared__ float sh[32];
    int b = blockIdx.x;
    int tid = threadIdx.x;
    float v = (tid < NSP) ? pol[b * NTOK + 1 + tid] : 0.f;
    float s = blockReduceSum(v, sh);
    if (tid == 0) den[b] = s;
}

__global__ void p1_k(const float* __restrict__ x,
                     const float* __restrict__ lnw, const float* __restrict__ lnb,
                     const float* __restrict__ Win, const float* __restrict__ bin,
                     float* __restrict__ ph)
{
    int bn = blockIdx.x;
    int b = bn / NSP, n = bn % NSP;
    int wid = threadIdx.x >> 5, lane = threadIdx.x & 31;
    __shared__ float sh[NHEAD][HDIM];

    const float* xr = x + ((long long)(b * NTOK + 1 + n)) * CDIM + wid * HDIM;
    float v0 = xr[lane], v1 = xr[lane + 32];
    float s = v0 + v1;
    #pragma unroll
    for (int o = 16; o; o >>= 1) s += __shfl_xor_sync(0xffffffffu, s, o);
    float m = s * (1.f / 64.f);
    float d0 = v0 - m, d1 = v1 - m;
    float q = d0*d0 + d1*d1;
    #pragma unroll
    for (int o = 16; o; o >>= 1) q += __shfl_xor_sync(0xffffffffu, q, o);
    float rs = rsqrtf(q * (1.f / 64.f) + 1e-5f);
    sh[wid][lane]      = d0 * rs * lnw[lane]      + lnb[lane];
    sh[wid][lane + 32] = d1 * rs * lnw[lane + 32] + lnb[lane + 32];
    __syncwarp();

    float a0 = bin[lane], a1 = bin[lane + 32];
    const float* w0 = Win + lane * 64;
    const float* w1 = Win + (lane + 32) * 64;
    #pragma unroll 8
    for (int e = 0; e < 64; e++) {
        float he = sh[wid][e];
        a0 += w0[e] * he;
        a1 += w1[e] * he;
    }
    float* o = ph + ((long long)bn * NHEAD + wid) * HDIM;
    o[lane]      = gelu_f(a0);
    o[lane + 32] = gelu_f(a1);
}

__global__ void p2_k(const float* __restrict__ ph, const float* __restrict__ pol,
                     const float* __restrict__ den, float* __restrict__ glob)
{
    int bh = blockIdx.x;
    int b = bh / NHEAD, h = bh % NHEAD;
    int tid = threadIdx.x;
    int d = tid & 31, seg = tid >> 5;
    float s = 0.f;
    for (int n = seg; n < NSP; n += 8)
        s += ph[(((long long)(b * NSP + n)) * NHEAD + h) * HDIM + 32 + d]
             * pol[b * NTOK + 1 + n];
    __shared__ float sh[8][32];
    sh[seg][d] = s;
    __syncthreads();
    if (seg == 0) {
        float t = 0.f;
        #pragma unroll
        for (int k = 0; k < 8; k++) t += sh[k][d];
        glob[(b * NHEAD + h) * 32 + d] = t / den[b];
    }
}

__global__ void p3_k(const float* __restrict__ ph, const float* __restrict__ glob,
                     const float* __restrict__ W1, const float* __restrict__ b1,
                     const float* __restrict__ W2, const float* __restrict__ b2,
                     const float* __restrict__ W3, const float* __restrict__ b3,
                     const float* __restrict__ gum, float* __restrict__ pol)
{
    int bn = blockIdx.x;
    int b = bn / NSP, n = bn % NSP;
    int wid = threadIdx.x >> 5, lane = threadIdx.x & 31;
    __shared__ float h2[NHEAD][64];
    __shared__ float o1[NHEAD][32];
    __shared__ float o2[NHEAD][16];
    __shared__ float zz[NHEAD][2];

    const float* hin = ph + ((long long)bn * NHEAD + wid) * HDIM;
    h2[wid][lane]      = hin[lane];
    h2[wid][32 + lane] = glob[(b * NHEAD + wid) * 32 + lane];
    __syncwarp();
    {
        float a = b1[lane];
        const float* wr = W1 + lane * 64;
        #pragma unroll 8
        for (int e = 0; e < 64; e++) a += wr[e] * h2[wid][e];
        o1[wid][lane] = gelu_f(a);
    }
    __syncwarp();
    if (lane < 16) {
        float a = b2[lane];
        const float* wr = W2 + lane * 32;
        #pragma unroll 8
        for (int e = 0; e < 32; e++) a += wr[e] * o1[wid][e];
        o2[wid][lane] = gelu_f(a);
    }
    __syncwarp();
    if (lane < 2) {
        float a = b3[lane];
        const float* wr = W3 + lane * 16;
        #pragma unroll
        for (int e = 0; e < 16; e++) a += wr[e] * o2[wid][e];
        zz[wid][lane] = a;
    }
    __syncthreads();
    if (threadIdx.x == 0) {
        float s0 = 0.f, s1 = 0.f;
        #pragma unroll
        for (int h = 0; h < NHEAD; h++) {
            float z0 = zz[h][0], z1 = zz[h][1];
            float mx = fmaxf(z0, z1);
            float lse = mx + logf(expf(z0 - mx) + expf(z1 - mx));
            s0 += z0 - lse;
            s1 += z1 - lse;
        }
        s0 *= (1.f / 6.f); s1 *= (1.f / 6.f);
        float u0 = gum[((long long)b * NSP + n) * 2 + 0];
        float u1 = gum[((long long)b * NSP + n) * 2 + 1];
        float g0 = -logf(-logf(u0 + 1e-10f) + 1e-10f);
        float g1 = -logf(-logf(u1 + 1e-10f) + 1e-10f);
        int idx = b * NTOK + 1 + n;
        float keep = (s0 + g0 >= s1 + g1) ? pol[idx] : 0.f;
        pol[idx] = keep;
    }
}

/* ---------------- host-side ------------------------------------------------ */
extern "C" void kernel_launch(void* const* d_in, const int* in_sizes, int n_in,
                              void* d_out, int out_size)
{
    const float* in_x     = (const float*)d_in[0];
    const float* in_cls   = (const float*)d_in[1];
    const float* in_pol   = (const float*)d_in[2];
    const float* in_gum   = (const float*)d_in[3];
    const float* ln1_w    = (const float*)d_in[4];
    const float* ln1_b    = (const float*)d_in[5];
    const float* qkv_w    = (const float*)d_in[6];
    const float* qkv_b    = (const float*)d_in[7];
    const float* proj_w   = (const float*)d_in[8];
    const float* proj_b   = (const float*)d_in[9];
    const float* ln2_w    = (const float*)d_in[10];
    const float* ln2_b    = (const float*)d_in[11];
    const float* fc1_w    = (const float*)d_in[12];
    const float* fc1_b    = (const float*)d_in[13];
    const float* fc2_w    = (const float*)d_in[14];
    const float* fc2_b    = (const float*)d_in[15];
    const float* p_ln_w   = (const float*)d_in[16];
    const float* p_ln_b   = (const float*)d_in[17];
    const float* p_in_w   = (const float*)d_in[18];
    const float* p_in_b   = (const float*)d_in[19];
    const float* p_o1_w   = (const float*)d_in[20];
    const float* p_o1_b   = (const float*)d_in[21];
    const float* p_o2_w   = (const float*)d_in[22];
    const float* p_o2_b   = (const float*)d_in[23];
    const float* p_o3_w   = (const float*)d_in[24];
    const float* p_o3_b   = (const float*)d_in[25];

    cudaFuncSetAttribute(hgemm_k<0, true >, cudaFuncAttributeMaxDynamicSharedMemorySize, DENSE_SMEM);
    cudaFuncSetAttribute(hgemm_k<1, true >, cudaFuncAttributeMaxDynamicSharedMemorySize, DENSE_SMEM);
    cudaFuncSetAttribute(hgemm_k<2, false>, cudaFuncAttributeMaxDynamicSharedMemorySize, DENSE_SMEM);
    cudaFuncSetAttribute(attn_fused_k,      cudaFuncAttributeMaxDynamicSharedMemorySize, FUSED_SMEM);

    float  *px, *ppol, *pph, *pglob, *pden;
    __half *ph16, *pqkv16, *pao16, *pffn16, *pwh;
    cudaGetSymbolAddress((void**)&px,     g_x);
    cudaGetSymbolAddress((void**)&ph16,   g_h16);
    cudaGetSymbolAddress((void**)&pqkv16, g_qkv16);
    cudaGetSymbolAddress((void**)&pao16,  g_ao16);
    cudaGetSymbolAddress((void**)&pffn16, g_ffn16);
    cudaGetSymbolAddress((void**)&pwh,    g_wh);
    cudaGetSymbolAddress((void**)&ppol,   g_pol);
    cudaGetSymbolAddress((void**)&pph,    g_ph);
    cudaGetSymbolAddress((void**)&pglob,  g_glob);
    cudaGetSymbolAddress((void**)&pden,   g_den);

    /* weights fp32 -> fp16 scratch (per-layer packed, half2 vectorized) */
    {
        cvtw_k<<<dim3((QKVDIM * CDIM / 2 + 255) / 256, DEPTHN), 256>>>(qkv_w,  pwh, QKVDIM * CDIM, W_QKV_OFF);
        cvtw_k<<<dim3((CDIM * CDIM / 2 + 255) / 256, DEPTHN), 256>>>(proj_w, pwh, CDIM * CDIM,   W_PROJ_OFF);
        cvtw_k<<<dim3((FFDIM * CDIM / 2 + 255) / 256, DEPTHN), 256>>>(fc1_w,  pwh, FFDIM * CDIM,  W_FC1_OFF);
        cvtw_k<<<dim3((CDIM * FFDIM / 2 + 255) / 256, DEPTHN), 256>>>(fc2_w,  pwh, CDIM * FFDIM,  W_FC2_OFF);
    }

    /* init: tiled transpose + cls/policy */
    init_tp_k<<<dim3(7, 12, BATCH), dim3(32, 8)>>>(in_x, px);
    init_aux_k<<<(BATCH * CDIM + 255) / 256, 256>>>(in_cls, in_pol, px, ppol);

    int pc = 0;
    for (int i = 0; i < DEPTHN; i++) {
        const __half* wl = pwh + (long long)i * LW;
        if (i == 3 || i == 6 || i == 9) {
            den_k<<<BATCH, 256>>>(ppol, pden);
            p1_k<<<BATCH * NSP, 192>>>(px,
                p_ln_w + pc * HDIM, p_ln_b + pc * HDIM,
                p_in_w + pc * HDIM * HDIM, p_in_b + pc * HDIM, pph);
            p2_k<<<BATCH * NHEAD, 256>>>(pph, ppol, pden, pglob);
            p3_k<<<BATCH * NSP, 192>>>(pph, pglob,
                p_o1_w + pc * 32 * 64, p_o1_b + pc * 32,
                p_o2_w + pc * 16 * 32, p_o2_b + pc * 16,
                p_o3_w + pc * 2 * 16,  p_o3_b + pc * 2,
                in_gum + (long long)pc * BATCH * NSP * 2, ppol);
            pc++;
        }

        ln_k<<<MROWS / 8, 256>>>(px, ln1_w + i * CDIM, ln1_b + i * CDIM, ph16, 1e-6f);

        hgemm_k<0, true><<<dim3(QKVDIM / 128, MROWS / 128), 256, DENSE_SMEM>>>(
            ph16, wl + W_QKV_OFF, qkv_b + i * QKVDIM, nullptr, pqkv16,
            CDIM, CDIM, CDIM, QKVDIM);

        attn_fused_k<<<dim3(2, BATCH * NHEAD), 256, FUSED_SMEM>>>(pqkv16, ppol, pao16);

        hgemm_k<2, false><<<dim3(CDIM / 128, MROWS / 128), 256, DENSE_SMEM>>>(
            pao16, wl + W_PROJ_OFF, proj_b + i * CDIM, px, px,
            CDIM, CDIM, CDIM, CDIM);

        ln_k<<<MROWS / 8, 256>>>(px, ln2_w + i * CDIM, ln2_b + i * CDIM, ph16, 1e-6f);

        hgemm_k<1, true><<<dim3(FFDIM / 128, MROWS / 128), 256, DENSE_SMEM>>>(
            ph16, wl + W_FC1_OFF, fc1_b + i * FFDIM, nullptr, pffn16,
            CDIM, CDIM, CDIM, FFDIM);

        hgemm_k<2, false><<<dim3(CDIM / 128, MROWS / 128), 256, DENSE_SMEM>>>(
            pffn16, wl + W_FC2_OFF, fc2_b + i * CDIM, px, px,
            FFDIM, FFDIM, FFDIM, CDIM);
    }

    /* final: tiled transpose + cls tail */
    final_tp_k<<<dim3(7, 12, BATCH), dim3(32, 8)>>>(px, (float*)d_out);
    final_aux_k<<<(BATCH * CDIM + 255) / 256, 256>>>(px, (float*)d_out);
}

// round 16
// speedup vs baseline: 1.0700x; 1.0700x over previous
#include <cuda_runtime.h>
#include <cuda_fp16.h>
#include <math.h>
#include <stdint.h>

#define DEPTHN 12
#define BATCH 128
#define NTOK 197
#define NSP 196
#define CDIM 384
#define NHEAD 6
#define HDIM 64
#define MROWS (BATCH*NTOK)      /* 25216 */
#define FFDIM 1536
#define QKVDIM 1152

/* per-layer packed half-weight layout */
#define W_QKV_OFF 0
#define W_PROJ_OFF 442368
#define W_FC1_OFF 589824
#define W_FC2_OFF 1179648
#define LW 1769472

/* ---------------- scratch (device globals; zero-initialized) ------------- */
__device__ float  g_x   [MROWS*CDIM];
__device__ __half g_h16 [MROWS*CDIM];
__device__ __half g_qkv16[MROWS*QKVDIM];
__device__ __half g_ao16[MROWS*CDIM];
__device__ __half g_ffn16[(long long)MROWS*FFDIM];
__device__ __half g_wh  [(long long)DEPTHN*LW];
__device__ float  g_pol [BATCH*NTOK];
__device__ float  g_ph  [BATCH*NSP*NHEAD*HDIM];
__device__ float  g_glob[BATCH*NHEAD*32];
__device__ float  g_den [BATCH];

__device__ __forceinline__ float gelu_f(float x) {
    return 0.5f * x * (1.0f + erff(x * 0.70710678118654752440f));
}

__device__ __forceinline__ uint32_t smem_u32(const void* p) {
    uint32_t a;
    asm("{ .reg .u64 t; cvta.to.shared.u64 t, %1; cvt.u32.u64 %0, t; }" : "=r"(a) : "l"(p));
    return a;
}

__device__ __forceinline__ uint32_t pack_h2(float lo, float hi) {
    uint32_t r;
    asm("cvt.rn.f16x2.f32 %0, %1, %2;" : "=r"(r) : "f"(hi), "f"(lo));
    return r;
}

__device__ __forceinline__ void cp_async16(uint32_t saddr, const void* g) {
    asm volatile("cp.async.cg.shared.global [%0], [%1], 16;" :: "r"(saddr), "l"(g));
}
#define CP_COMMIT() asm volatile("cp.async.commit_group;" ::: "memory")
#define CP_WAIT(n)  asm volatile("cp.async.wait_group %0;" :: "n"(n) : "memory")

__device__ __forceinline__ void ldsm_x4(uint32_t& r0, uint32_t& r1,
                                        uint32_t& r2, uint32_t& r3, uint32_t a) {
    asm volatile("ldmatrix.sync.aligned.m8n8.x4.shared.b16 {%0,%1,%2,%3}, [%4];"
                 : "=r"(r0), "=r"(r1), "=r"(r2), "=r"(r3) : "r"(a));
}
__device__ __forceinline__ void ldsm_x2(uint32_t& r0, uint32_t& r1, uint32_t a) {
    asm volatile("ldmatrix.sync.aligned.m8n8.x2.shared.b16 {%0,%1}, [%2];"
                 : "=r"(r0), "=r"(r1) : "r"(a));
}

__device__ __forceinline__ void mma_f16(
    float& d0, float& d1, float& d2, float& d3,
    uint32_t a0, uint32_t a1, uint32_t a2, uint32_t a3,
    uint32_t b0, uint32_t b1)
{
    asm volatile(
        "mma.sync.aligned.m16n8k16.row.col.f32.f16.f16.f32 "
        "{%0,%1,%2,%3}, {%4,%5,%6,%7}, {%8,%9}, {%0,%1,%2,%3};"
        : "+f"(d0), "+f"(d1), "+f"(d2), "+f"(d3)
        : "r"(a0), "r"(a1), "r"(a2), "r"(a3), "r"(b0), "r"(b1));
}

/* ---------------- weights fp32 -> fp16, all 4 segments in one launch ----- */
__global__ void cvtw_all_k(const float* __restrict__ qkv_w,
                           const float* __restrict__ proj_w,
                           const float* __restrict__ fc1_w,
                           const float* __restrict__ fc2_w,
                           __half* __restrict__ dstbase)
{
    const int l = blockIdx.z >> 2, seg = blockIdx.z & 3;
    const float* src;
    int perL, off;
    switch (seg) {
        case 0:  src = qkv_w;  perL = QKVDIM * CDIM; off = W_QKV_OFF;  break;
        case 1:  src = proj_w; perL = CDIM * CDIM;   off = W_PROJ_OFF; break;
        case 2:  src = fc1_w;  perL = FFDIM * CDIM;  off = W_FC1_OFF;  break;
        default: src = fc2_w;  perL = CDIM * FFDIM;  off = W_FC2_OFF;  break;
    }
    long long i = ((long long)blockIdx.x * blockDim.x + threadIdx.x) * 2;
    if (i < perL) {
        float2 v = *(const float2*)(src + (long long)l * perL + i);
        *(__half2*)(dstbase + (long long)l * LW + off + i) = __floats2half2_rn(v.x, v.y);
    }
}

/* ================= dense fp16 HMMA GEMM (R8/R14 best config) =============
 * C[m,n] = sum_k A[m,k]*B[n,k] + bias[n]   (EPI: 0 none, 1 gelu, 2 +R)
 * 256 threads, 8 warps (2M x 4N), warp 64x32; ldmatrix; 2-stage cp.async.
 */
#define DENSE_SMEM 73728

template<int EPI, bool OUTH>
__global__ void __launch_bounds__(256, 2)
hgemm_k(const __half* __restrict__ A, const __half* __restrict__ B,
        const float* __restrict__ bias, const float* __restrict__ R,
        void* __restrict__ Cv, int K, int lda, int ldb, int ldc)
{
    extern __shared__ __half hsm[];
    __half* As = hsm;              /* [2][128*72] */
    __half* Bs = hsm + 18432;
    const uint32_t asb = smem_u32(As), bsb = smem_u32(Bs);

    const int tid = threadIdx.x, wid = tid >> 5, lane = tid & 31;
    const int lane4 = lane >> 2, lanek = lane & 3;
    const int warpM = wid & 1, warpN = wid >> 1;
    const int m0 = blockIdx.y * 128, n0 = blockIdx.x * 128;

    const int mat = lane >> 3;
    const int arow = (lane & 7) + (mat & 1) * 8;
    const int acol = (mat >> 1) * 8;
    const int brow = lane & 7;
    const int bcol = ((lane >> 3) & 1) * 8;

    float acc[4][4][4];
    #pragma unroll
    for (int i = 0; i < 4; i++)
        #pragma unroll
        for (int j = 0; j < 4; j++)
            #pragma unroll
            for (int r = 0; r < 4; r++) acc[i][j][r] = 0.f;

#define HISSUE(t_, s_) do {                                                     \
    int k0_ = (t_) * 64;                                                        \
    _Pragma("unroll")                                                           \
    for (int i_ = 0; i_ < 4; i_++) {                                            \
        int idx_ = tid + 256 * i_;                                              \
        int row_ = idx_ >> 3, ch_ = idx_ & 7;                                   \
        uint32_t so_ = (uint32_t)(((s_) * 9216 + row_ * 72 + ch_ * 8) * 2);     \
        cp_async16(asb + so_, A + (size_t)(m0 + row_) * lda + k0_ + ch_ * 8);   \
        cp_async16(bsb + so_, B + (size_t)(n0 + row_) * ldb + k0_ + ch_ * 8);   \
    }                                                                           \
    CP_COMMIT();                                                                \
} while (0)

    const int T = K >> 6;
    HISSUE(0, 0);

    for (int t = 0; t < T; t++) {
        int p = t & 1;
        if (t + 1 < T) { HISSUE(t + 1, p ^ 1); CP_WAIT(1); }
        else           { CP_WAIT(0); }
        __syncthreads();

        uint32_t aAddr[4], bAddr[4];
        #pragma unroll
        for (int mf = 0; mf < 4; mf++)
            aAddr[mf] = asb + (uint32_t)((p * 9216 + (warpM * 64 + mf * 16 + arow) * 72 + acol) * 2);
        #pragma unroll
        for (int nf = 0; nf < 4; nf++)
            bAddr[nf] = bsb + (uint32_t)((p * 9216 + (warpN * 32 + nf * 8 + brow) * 72 + bcol) * 2);

        #pragma unroll
        for (int ks = 0; ks < 4; ks++) {
            uint32_t a[4][4], b[4][2];
            #pragma unroll
            for (int mf = 0; mf < 4; mf++)
                ldsm_x4(a[mf][0], a[mf][1], a[mf][2], a[mf][3], aAddr[mf] + ks * 32);
            #pragma unroll
            for (int nf = 0; nf < 4; nf++)
                ldsm_x2(b[nf][0], b[nf][1], bAddr[nf] + ks * 32);
            #pragma unroll
            for (int mf = 0; mf < 4; mf++)
                #pragma unroll
                for (int nf = 0; nf < 4; nf++)
                    mma_f16(acc[mf][nf][0], acc[mf][nf][1],
                            acc[mf][nf][2], acc[mf][nf][3],
                            a[mf][0], a[mf][1], a[mf][2], a[mf][3],
                            b[nf][0], b[nf][1]);
        }
        if (t + 1 < T) __syncthreads();
    }
#undef HISSUE

    /* epilogue */
    #pragma unroll
    for (int mf = 0; mf < 4; mf++) {
        int m = m0 + warpM * 64 + mf * 16 + lane4;
        #pragma unroll
        for (int nf = 0; nf < 4; nf++) {
            int n = n0 + warpN * 32 + nf * 8 + lanek * 2;
            float bz0 = bias ? __ldg(bias + n)     : 0.f;
            float bz1 = bias ? __ldg(bias + n + 1) : 0.f;
            size_t gi0 = (size_t)m * ldc + n;
            size_t gi1 = (size_t)(m + 8) * ldc + n;
            float v0 = acc[mf][nf][0] + bz0;
            float v1 = acc[mf][nf][1] + bz1;
            float v2 = acc[mf][nf][2] + bz0;
            float v3 = acc[mf][nf][3] + bz1;
            if (EPI == 1) {
                v0 = gelu_f(v0); v1 = gelu_f(v1);
                v2 = gelu_f(v2); v3 = gelu_f(v3);
            } else if (EPI == 2) {
                v0 += R[gi0]; v1 += R[gi0 + 1];
                v2 += R[gi1]; v3 += R[gi1 + 1];
            }
            if (OUTH) {
                __half* C = (__half*)Cv;
                *(__half2*)(C + gi0) = __floats2half2_rn(v0, v1);
                *(__half2*)(C + gi1) = __floats2half2_rn(v2, v3);
            } else {
                float* C = (float*)Cv;
                *(float2*)(C + gi0) = make_float2(v0, v1);
                *(float2*)(C + gi1) = make_float2(v2, v3);
            }
        }
    }
}

/* ================= fused attention: S=QK^T -> softmax -> O=P@V =========== */
#define FUSED_SMEM 90112

__global__ void __launch_bounds__(256)
attn_fused_k(const __half* __restrict__ qkv, const float* __restrict__ pol,
             __half* __restrict__ ao)
{
    extern __shared__ __half ssm[];
    __half* Qs = ssm;                       /* [128][72]  */
    __half* Ks = ssm + 9216;                /* [256][72]  */
    __half* Vs = ssm + 27648;               /* [64][264]  */
    float* pol_s = (float*)(ssm + 44544);

    const int tid = threadIdx.x, wid = tid >> 5, lane = tid & 31;
    const int bh = blockIdx.y, b = bh / NHEAD, h = bh % NHEAD;
    const int m0 = blockIdx.x * 128;

    const int mat = lane >> 3;
    const int arow = (lane & 7) + (mat & 1) * 8;
    const int acol = (mat >> 1) * 8;
    const int brow = (lane & 7) + ((lane >> 4) << 3);
    const int bcol = ((lane >> 3) & 1) * 8;
    const int vrow = lane & 7;
    const int vcol = ((lane >> 3) & 1) * 8;

    const __half* qb = qkv + (size_t)b * NTOK * QKVDIM + h * HDIM;
    const __half* kb = qb + CDIM;
    const __half* vb = qb + 2 * CDIM;

    for (int i = tid; i < NTOK; i += 256) pol_s[i] = pol[b * NTOK + i];

    const uint4 zero4 = make_uint4(0, 0, 0, 0);
    #pragma unroll
    for (int p = 0; p < 2; p++) {
        int row = (tid >> 2) + p * 64;
        int col = (tid & 3) * 16;
        uint4 v0 = zero4, v1 = zero4;
        if (m0 + row < NTOK) {
            const __half* s = qb + (size_t)(m0 + row) * QKVDIM + col;
            v0 = *(const uint4*)s; v1 = *(const uint4*)(s + 8);
        }
        *(uint4*)&Qs[row * 72 + col]     = v0;
        *(uint4*)&Qs[row * 72 + col + 8] = v1;
    }
    #pragma unroll
    for (int p = 0; p < 4; p++) {
        int row = (tid >> 2) + p * 64;
        int col = (tid & 3) * 16;
        uint4 v0 = zero4, v1 = zero4;
        if (row < NTOK) {
            const __half* s = kb + (size_t)row * QKVDIM + col;
            v0 = *(const uint4*)s; v1 = *(const uint4*)(s + 8);
        }
        *(uint4*)&Ks[row * 72 + col]     = v0;
        *(uint4*)&Ks[row * 72 + col + 8] = v1;
    }
    {
        int n = tid & 63, k4 = tid >> 6;
        #pragma unroll
        for (int i = 0; i < 64; i++) {
            int k = k4 + 4 * i;
            __half v = (k < NTOK) ? vb[(size_t)k * QKVDIM + n] : __half(0.f);
            Vs[n * 264 + k] = v;
        }
    }
    __syncthreads();

    /* ---- S = Q @ K^T ---- */
    float acc[32][4];
    #pragma unroll
    for (int j = 0; j < 32; j++)
        #pragma unroll
        for (int r = 0; r < 4; r++) acc[j][r] = 0.f;

    const uint32_t qsb = smem_u32(Qs), ksb = smem_u32(Ks), vsb = smem_u32(Vs);
    const uint32_t aBase = qsb + (uint32_t)(((wid * 16 + arow) * 72 + acol) * 2);
    const uint32_t bBase = ksb + (uint32_t)((brow * 72 + bcol) * 2);

    #pragma unroll
    for (int ks = 0; ks < 4; ks++) {
        uint32_t a0, a1, a2, a3;
        ldsm_x4(a0, a1, a2, a3, aBase + ks * 32);
        #pragma unroll
        for (int ng = 0; ng < 16; ng++) {
            uint32_t b0, b1, b2, b3;
            ldsm_x4(b0, b1, b2, b3, bBase + (uint32_t)(ng * 16 * 72 * 2) + ks * 32);
            mma_f16(acc[ng*2][0], acc[ng*2][1], acc[ng*2][2], acc[ng*2][3],
                    a0, a1, a2, a3, b0, b1);
            mma_f16(acc[ng*2+1][0], acc[ng*2+1][1], acc[ng*2+1][2], acc[ng*2+1][3],
                    a0, a1, a2, a3, b2, b3);
        }
    }

    /* ---- in-register policy softmax ---- */
    const int rr = lane >> 2, t = lane & 3;
    const int gm1 = m0 + wid * 16 + rr;
    const int gm2 = gm1 + 8;

    #pragma unroll
    for (int j = 0; j < 32; j++) {
        acc[j][0] *= 0.125f; acc[j][1] *= 0.125f;
        acc[j][2] *= 0.125f; acc[j][3] *= 0.125f;
    }

    float mx1 = -1e30f, mx2 = -1e30f;
    #pragma unroll
    for (int j = 0; j < 32; j++) {
        int col = j * 8 + t * 2;
        if (col < NTOK)     { mx1 = fmaxf(mx1, acc[j][0]); mx2 = fmaxf(mx2, acc[j][2]); }
        if (col + 1 < NTOK) { mx1 = fmaxf(mx1, acc[j][1]); mx2 = fmaxf(mx2, acc[j][3]); }
    }
    mx1 = fmaxf(mx1, __shfl_xor_sync(0xffffffffu, mx1, 1));
    mx1 = fmaxf(mx1, __shfl_xor_sync(0xffffffffu, mx1, 2));
    mx2 = fmaxf(mx2, __shfl_xor_sync(0xffffffffu, mx2, 1));
    mx2 = fmaxf(mx2, __shfl_xor_sync(0xffffffffu, mx2, 2));

    float sum1 = 0.f, sum2 = 0.f;
    #pragma unroll
    for (int j = 0; j < 32; j++) {
        int col = j * 8 + t * 2;
        if (col < NTOK) {
            float ap = pol_s[col];
            float a1v = (col == gm1) ? 1.0f : ap;
            float a2v = (col == gm2) ? 1.0f : ap;
            float e1 = __expf(acc[j][0] - mx1) * a1v; acc[j][0] = e1; sum1 += e1;
            float e2 = __expf(acc[j][2] - mx2) * a2v; acc[j][2] = e2; sum2 += e2;
        } else { acc[j][0] = 0.f; acc[j][2] = 0.f; }
        if (col + 1 < NTOK) {
            float ap = pol_s[col + 1];
            float a1v = (col + 1 == gm1) ? 1.0f : ap;
            float a2v = (col + 1 == gm2) ? 1.0f : ap;
            float e1 = __expf(acc[j][1] - mx1) * a1v; acc[j][1] = e1; sum1 += e1;
            float e2 = __expf(acc[j][3] - mx2) * a2v; acc[j][3] = e2; sum2 += e2;
        } else { acc[j][1] = 0.f; acc[j][3] = 0.f; }
    }
    sum1 += __shfl_xor_sync(0xffffffffu, sum1, 1);
    sum1 += __shfl_xor_sync(0xffffffffu, sum1, 2);
    sum2 += __shfl_xor_sync(0xffffffffu, sum2, 1);
    sum2 += __shfl_xor_sync(0xffffffffu, sum2, 2);
    float inv1 = 1.0f / sum1, inv2 = 1.0f / sum2;

    /* ---- pack P: C-fragment layout -> A-fragments ---- */
    uint32_t pa[16][4];
    #pragma unroll
    for (int g = 0; g < 16; g++) {
        pa[g][0] = pack_h2(acc[2*g][0]   * inv1, acc[2*g][1]   * inv1);
        pa[g][1] = pack_h2(acc[2*g][2]   * inv2, acc[2*g][3]   * inv2);
        pa[g][2] = pack_h2(acc[2*g+1][0] * inv1, acc[2*g+1][1] * inv1);
        pa[g][3] = pack_h2(acc[2*g+1][2] * inv2, acc[2*g+1][3] * inv2);
    }

    /* ---- O = P @ V ---- */
    float oacc[8][4];
    #pragma unroll
    for (int nf = 0; nf < 8; nf++)
        #pragma unroll
        for (int r = 0; r < 4; r++) oacc[nf][r] = 0.f;

    uint32_t vAddr[8];
    #pragma unroll
    for (int nf = 0; nf < 8; nf++)
        vAddr[nf] = vsb + (uint32_t)(((nf * 8 + vrow) * 264 + vcol) * 2);

    #pragma unroll
    for (int g = 0; g < 16; g++) {
        #pragma unroll
        for (int nf = 0; nf < 8; nf++) {
            uint32_t b0, b1;
            ldsm_x2(b0, b1, vAddr[nf] + g * 32);
            mma_f16(oacc[nf][0], oacc[nf][1], oacc[nf][2], oacc[nf][3],
                    pa[g][0], pa[g][1], pa[g][2], pa[g][3], b0, b1);
        }
    }

    /* ---- write O ---- */
    #pragma unroll
    for (int nf = 0; nf < 8; nf++) {
        int n = nf * 8 + t * 2;
        if (gm1 < NTOK)
            *(__half2*)(ao + (size_t)(b * NTOK + gm1) * CDIM + h * HDIM + n) =
                __floats2half2_rn(oacc[nf][0], oacc[nf][1]);
        if (gm2 < NTOK)
            *(__half2*)(ao + (size_t)(b * NTOK + gm2) * CDIM + h * HDIM + n) =
                __floats2half2_rn(oacc[nf][2], oacc[nf][3]);
    }
}

/* ---------------- block reductions --------------------------------------- */
__device__ __forceinline__ float blockReduceSum(float v, float* sh) {
    int tid = threadIdx.x, lane = tid & 31, w = tid >> 5;
    #pragma unroll
    for (int o = 16; o; o >>= 1) v += __shfl_xor_sync(0xffffffffu, v, o);
    if (lane == 0) sh[w] = v;
    __syncthreads();
    int nw = (blockDim.x + 31) >> 5;
    v = (tid < nw) ? sh[tid] : 0.f;
    if (w == 0) {
        #pragma unroll
        for (int o = 16; o; o >>= 1) v += __shfl_xor_sync(0xffffffffu, v, o);
        if (lane == 0) sh[0] = v;
    }
    __syncthreads();
    float r = sh[0];
    __syncthreads();
    return r;
}

/* ---------------- LayerNorm: warp-per-row, float4 I/O -------------------- */
__global__ void __launch_bounds__(256)
ln_k(const float* __restrict__ x, const float* __restrict__ w,
     const float* __restrict__ bb, __half* __restrict__ out, float eps)
{
    const int wid = threadIdx.x >> 5, lane = threadIdx.x & 31;
    const long long row = (long long)blockIdx.x * 8 + wid;
    const float4* xr = (const float4*)(x + row * CDIM);

    float4 v0 = xr[lane], v1 = xr[lane + 32], v2 = xr[lane + 64];
    float s = v0.x + v0.y + v0.z + v0.w
            + v1.x + v1.y + v1.z + v1.w
            + v2.x + v2.y + v2.z + v2.w;
    #pragma unroll
    for (int o = 16; o; o >>= 1) s += __shfl_xor_sync(0xffffffffu, s, o);
    float m = s * (1.f / 384.f);

    float q = (v0.x-m)*(v0.x-m) + (v0.y-m)*(v0.y-m) + (v0.z-m)*(v0.z-m) + (v0.w-m)*(v0.w-m)
            + (v1.x-m)*(v1.x-m) + (v1.y-m)*(v1.y-m) + (v1.z-m)*(v1.z-m) + (v1.w-m)*(v1.w-m)
            + (v2.x-m)*(v2.x-m) + (v2.y-m)*(v2.y-m) + (v2.z-m)*(v2.z-m) + (v2.w-m)*(v2.w-m);
    #pragma unroll
    for (int o = 16; o; o >>= 1) q += __shfl_xor_sync(0xffffffffu, q, o);
    float rs = rsqrtf(q * (1.f / 384.f) + eps);

    const float4* wv = (const float4*)w;
    const float4* bv = (const float4*)bb;
    __half* orow = out + row * CDIM;

    #pragma unroll
    for (int p = 0; p < 3; p++) {
        float4 vv = (p == 0) ? v0 : (p == 1) ? v1 : v2;
        float4 ww = wv[lane + p * 32];
        float4 bbv = bv[lane + p * 32];
        uint32_t lo = pack_h2((vv.x - m) * rs * ww.x + bbv.x,
                              (vv.y - m) * rs * ww.y + bbv.y);
        uint32_t hi = pack_h2((vv.z - m) * rs * ww.z + bbv.z,
                              (vv.w - m) * rs * ww.w + bbv.w);
        uint2 o2 = make_uint2(lo, hi);
        *(uint2*)(orow + (lane + p * 32) * 4) = o2;
    }
}

/* ---------------- tiled transpose init / final --------------------------- */
__global__ void init_tp_k(const float* __restrict__ xin, float* __restrict__ x)
{
    __shared__ float t[32][33];
    int b = blockIdx.z;
    int hw0 = blockIdx.x * 32, c0 = blockIdx.y * 32;
    int tx = threadIdx.x, ty = threadIdx.y;
    #pragma unroll
    for (int i = 0; i < 32; i += 8) {
        int c = c0 + ty + i, hw = hw0 + tx;
        if (hw < NSP)
            t[ty + i][tx] = xin[((size_t)b * CDIM + c) * NSP + hw];
    }
    __syncthreads();
    #pragma unroll
    for (int i = 0; i < 32; i += 8) {
        int hw = hw0 + ty + i, c = c0 + tx;
        if (hw < NSP)
            x[((size_t)b * NTOK + 1 + hw) * CDIM + c] = t[tx][ty + i];
    }
}

__global__ void init_aux_k(const float* __restrict__ cls, const float* __restrict__ polin,
                           float* __restrict__ x, float* __restrict__ pol)
{
    int idx = blockIdx.x * blockDim.x + threadIdx.x;
    if (idx < BATCH * CDIM) {
        int b = idx / CDIM, c = idx % CDIM;
        x[(size_t)b * NTOK * CDIM + c] = cls[idx];
    }
    if (idx < BATCH * NTOK) pol[idx] = polin[idx];
}

__global__ void final_tp_k(const float* __restrict__ x, float* __restrict__ out)
{
    __shared__ float t[32][33];
    int b = blockIdx.z;
    int hw0 = blockIdx.x * 32, c0 = blockIdx.y * 32;
    int tx = threadIdx.x, ty = threadIdx.y;
    #pragma unroll
    for (int i = 0; i < 32; i += 8) {
        int hw = hw0 + ty + i, c = c0 + tx;
        if (hw < NSP)
            t[ty + i][tx] = x[((size_t)b * NTOK + 1 + hw) * CDIM + c];
    }
    __syncthreads();
    #pragma unroll
    for (int i = 0; i < 32; i += 8) {
        int c = c0 + ty + i, hw = hw0 + tx;
        if (hw < NSP)
            out[((size_t)b * CDIM + c) * NSP + hw] = t[tx][ty + i];
    }
}

__global__ void final_aux_k(const float* __restrict__ x, float* __restrict__ out)
{
    int idx = blockIdx.x * blockDim.x + threadIdx.x;
    if (idx < BATCH * CDIM) {
        int b = idx / CDIM, c = idx % CDIM;
        out[(size_t)BATCH * CDIM * NSP + idx] = x[(size_t)b * NTOK * CDIM + c];
    }
}

/* ---------------- predictor --------------------------------------------- */
__global__ void den_k(const float* __restrict__ pol, float* __restrict__ den)
{
    __shared__ float sh[32];
    int b = blockIdx.x;
    int tid = threadIdx.x;
    float v = (tid < NSP) ? pol[b * NTOK + 1 + tid] : 0.f;
    float s = blockReduceSum(v, sh);
    if (tid == 0) den[b] = s;
}

__global__ void p1_k(const float* __restrict__ x,
                     const float* __restrict__ lnw, const float* __restrict__ lnb,
                     const float* __restrict__ Win, const float* __restrict__ bin,
                     float* __restrict__ ph)
{
    int bn = blockIdx.x;
    int b = bn / NSP, n = bn % NSP;
    int wid = threadIdx.x >> 5, lane = threadIdx.x & 31;
    __shared__ float sh[NHEAD][HDIM];

    const float* xr = x + ((long long)(b * NTOK + 1 + n)) * CDIM + wid * HDIM;
    float v0 = xr[lane], v1 = xr[lane + 32];
    float s = v0 + v1;
    #pragma unroll
    for (int o = 16; o; o >>= 1) s += __shfl_xor_sync(0xffffffffu, s, o);
    float m = s * (1.f / 64.f);
    float d0 = v0 - m, d1 = v1 - m;
    float q = d0*d0 + d1*d1;
    #pragma unroll
    for (int o = 16; o; o >>= 1) q += __shfl_xor_sync(0xffffffffu, q, o);
    float rs = rsqrtf(q * (1.f / 64.f) + 1e-5f);
    sh[wid][lane]      = d0 * rs * lnw[lane]      + lnb[lane];
    sh[wid][lane + 32] = d1 * rs * lnw[lane + 32] + lnb[lane + 32];
    __syncwarp();

    float a0 = bin[lane], a1 = bin[lane + 32];
    const float* w0 = Win + lane * 64;
    const float* w1 = Win + (lane + 32) * 64;
    #pragma unroll 8
    for (int e = 0; e < 64; e++) {
        float he = sh[wid][e];
        a0 += w0[e] * he;
        a1 += w1[e] * he;
    }
    float* o = ph + ((long long)bn * NHEAD + wid) * HDIM;
    o[lane]      = gelu_f(a0);
    o[lane + 32] = gelu_f(a1);
}

__global__ void p2_k(const float* __restrict__ ph, const float* __restrict__ pol,
                     const float* __restrict__ den, float* __restrict__ glob)
{
    int bh = blockIdx.x;
    int b = bh / NHEAD, h = bh % NHEAD;
    int tid = threadIdx.x;
    int d = tid & 31, seg = tid >> 5;
    float s = 0.f;
    for (int n = seg; n < NSP; n += 8)
        s += ph[(((long long)(b * NSP + n)) * NHEAD + h) * HDIM + 32 + d]
             * pol[b * NTOK + 1 + n];
    __shared__ float sh[8][32];
    sh[seg][d] = s;
    __syncthreads();
    if (seg == 0) {
        float t = 0.f;
        #pragma unroll
        for (int k = 0; k < 8; k++) t += sh[k][d];
        glob[(b * NHEAD + h) * 32 + d] = t / den[b];
    }
}

__global__ void p3_k(const float* __restrict__ ph, const float* __restrict__ glob,
                     const float* __restrict__ W1, const float* __restrict__ b1,
                     const float* __restrict__ W2, const float* __restrict__ b2,
                     const float* __restrict__ W3, const float* __restrict__ b3,
                     const float* __restrict__ gum, float* __restrict__ pol)
{
    int bn = blockIdx.x;
    int b = bn / NSP, n = bn % NSP;
    int wid = threadIdx.x >> 5, lane = threadIdx.x & 31;
    __shared__ float h2[NHEAD][64];
    __shared__ float o1[NHEAD][32];
    __shared__ float o2[NHEAD][16];
    __shared__ float zz[NHEAD][2];

    const float* hin = ph + ((long long)bn * NHEAD + wid) * HDIM;
    h2[wid][lane]      = hin[lane];
    h2[wid][32 + lane] = glob[(b * NHEAD + wid) * 32 + lane];
    __syncwarp();
    {
        float a = b1[lane];
        const float* wr = W1 + lane * 64;
        #pragma unroll 8
        for (int e = 0; e < 64; e++) a += wr[e] * h2[wid][e];
        o1[wid][lane] = gelu_f(a);
    }
    __syncwarp();
    if (lane < 16) {
        float a = b2[lane];
        const float* wr = W2 + lane * 32;
        #pragma unroll 8
        for (int e = 0; e < 32; e++) a += wr[e] * o1[wid][e];
        o2[wid][lane] = gelu_f(a);
    }
    __syncwarp();
    if (lane < 2) {
        float a = b3[lane];
        const float* wr = W3 + lane * 16;
        #pragma unroll
        for (int e = 0; e < 16; e++) a += wr[e] * o2[wid][e];
        zz[wid][lane] = a;
    }
    __syncthreads();
    if (threadIdx.x == 0) {
        float s0 = 0.f, s1 = 0.f;
        #pragma unroll
        for (int h = 0; h < NHEAD; h++) {
            float z0 = zz[h][0], z1 = zz[h][1];
            float mx = fmaxf(z0, z1);
            float lse = mx + logf(expf(z0 - mx) + expf(z1 - mx));
            s0 += z0 - lse;
            s1 += z1 - lse;
        }
        s0 *= (1.f / 6.f); s1 *= (1.f / 6.f);
        float u0 = gum[((long long)b * NSP + n) * 2 + 0];
        float u1 = gum[((long long)b * NSP + n) * 2 + 1];
        float g0 = -logf(-logf(u0 + 1e-10f) + 1e-10f);
        float g1 = -logf(-logf(u1 + 1e-10f) + 1e-10f);
        int idx = b * NTOK + 1 + n;
        float keep = (s0 + g0 >= s1 + g1) ? pol[idx] : 0.f;
        pol[idx] = keep;
    }
}

/* ---------------- host-side ------------------------------------------------ */
extern "C" void kernel_launch(void* const* d_in, const int* in_sizes, int n_in,
                              void* d_out, int out_size)
{
    const float* in_x     = (const float*)d_in[0];
    const float* in_cls   = (const float*)d_in[1];
    const float* in_pol   = (const float*)d_in[2];
    const float* in_gum   = (const float*)d_in[3];
    const float* ln1_w    = (const float*)d_in[4];
    const float* ln1_b    = (const float*)d_in[5];
    const float* qkv_w    = (const float*)d_in[6];
    const float* qkv_b    = (const float*)d_in[7];
    const float* proj_w   = (const float*)d_in[8];
    const float* proj_b   = (const float*)d_in[9];
    const float* ln2_w    = (const float*)d_in[10];
    const float* ln2_b    = (const float*)d_in[11];
    const float* fc1_w    = (const float*)d_in[12];
    const float* fc1_b    = (const float*)d_in[13];
    const float* fc2_w    = (const float*)d_in[14];
    const float* fc2_b    = (const float*)d_in[15];
    const float* p_ln_w   = (const float*)d_in[16];
    const float* p_ln_b   = (const float*)d_in[17];
    const float* p_in_w   = (const float*)d_in[18];
    const float* p_in_b   = (const float*)d_in[19];
    const float* p_o1_w   = (const float*)d_in[20];
    const float* p_o1_b   = (const float*)d_in[21];
    const float* p_o2_w   = (const float*)d_in[22];
    const float* p_o2_b   = (const float*)d_in[23];
    const float* p_o3_w   = (const float*)d_in[24];
    const float* p_o3_b   = (const float*)d_in[25];

    cudaFuncSetAttribute(hgemm_k<0, true >, cudaFuncAttributeMaxDynamicSharedMemorySize, DENSE_SMEM);
    cudaFuncSetAttribute(hgemm_k<1, true >, cudaFuncAttributeMaxDynamicSharedMemorySize, DENSE_SMEM);
    cudaFuncSetAttribute(hgemm_k<2, false>, cudaFuncAttributeMaxDynamicSharedMemorySize, DENSE_SMEM);
    cudaFuncSetAttribute(attn_fused_k,      cudaFuncAttributeMaxDynamicSharedMemorySize, FUSED_SMEM);

    float  *px, *ppol, *pph, *pglob, *pden;
    __half *ph16, *pqkv16, *pao16, *pffn16, *pwh;
    cudaGetSymbolAddress((void**)&px,     g_x);
    cudaGetSymbolAddress((void**)&ph16,   g_h16);
    cudaGetSymbolAddress((void**)&pqkv16, g_qkv16);
    cudaGetSymbolAddress((void**)&pao16,  g_ao16);
    cudaGetSymbolAddress((void**)&pffn16, g_ffn16);
    cudaGetSymbolAddress((void**)&pwh,    g_wh);
    cudaGetSymbolAddress((void**)&ppol,   g_pol);
    cudaGetSymbolAddress((void**)&pph,    g_ph);
    cudaGetSymbolAddress((void**)&pglob,  g_glob);
    cudaGetSymbolAddress((void**)&pden,   g_den);

    /* weights fp32 -> fp16 scratch (single launch, all segments) */
    cvtw_all_k<<<dim3((FFDIM * CDIM / 2 + 255) / 256, 1, DEPTHN * 4), 256>>>(
        qkv_w, proj_w, fc1_w, fc2_w, pwh);

    /* init: tiled transpose + cls/policy */
    init_tp_k<<<dim3(7, 12, BATCH), dim3(32, 8)>>>(in_x, px);
    init_aux_k<<<(BATCH * CDIM + 255) / 256, 256>>>(in_cls, in_pol, px, ppol);

    int pc = 0;
    for (int i = 0; i < DEPTHN; i++) {
        const __half* wl = pwh + (long long)i * LW;
        if (i == 3 || i == 6 || i == 9) {
            den_k<<<BATCH, 256>>>(ppol, pden);
            p1_k<<<BATCH * NSP, 192>>>(px,
                p_ln_w + pc * HDIM, p_ln_b + pc * HDIM,
                p_in_w + pc * HDIM * HDIM, p_in_b + pc * HDIM, pph);
            p2_k<<<BATCH * NHEAD, 256>>>(pph, ppol, pden, pglob);
            p3_k<<<BATCH * NSP, 192>>>(pph, pglob,
                p_o1_w + pc * 32 * 64, p_o1_b + pc * 32,
                p_o2_w + pc * 16 * 32, p_o2_b + pc * 16,
                p_o3_w + pc * 2 * 16,  p_o3_b + pc * 2,
                in_gum + (long long)pc * BATCH * NSP * 2, ppol);
            pc++;
        }

        ln_k<<<MROWS / 8, 256>>>(px, ln1_w + i * CDIM, ln1_b + i * CDIM, ph16, 1e-6f);

        hgemm_k<0, true><<<dim3(QKVDIM / 128, MROWS / 128), 256, DENSE_SMEM>>>(
            ph16, wl + W_QKV_OFF, qkv_b + i * QKVDIM, nullptr, pqkv16,
            CDIM, CDIM, CDIM, QKVDIM);

        attn_fused_k<<<dim3(2, BATCH * NHEAD), 256, FUSED_SMEM>>>(pqkv16, ppol, pao16);

        hgemm_k<2, false><<<dim3(CDIM / 128, MROWS / 128), 256, DENSE_SMEM>>>(
            pao16, wl + W_PROJ_OFF, proj_b + i * CDIM, px, px,
            CDIM, CDIM, CDIM, CDIM);

        ln_k<<<MROWS / 8, 256>>>(px, ln2_w + i * CDIM, ln2_b + i * CDIM, ph16, 1e-6f);

        hgemm_k<1, true><<<dim3(FFDIM / 128, MROWS / 128), 256, DENSE_SMEM>>>(
            ph16, wl + W_FC1_OFF, fc1_b + i * FFDIM, nullptr, pffn16,
            CDIM, CDIM, CDIM, FFDIM);

        hgemm_k<2, false><<<dim3(CDIM / 128, MROWS / 128), 256, DENSE_SMEM>>>(
            pffn16, wl + W_FC2_OFF, fc2_b + i * CDIM, px, px,
            FFDIM, FFDIM, FFDIM, CDIM);
    }

    /* final: tiled transpose + cls tail */
    final_tp_k<<<dim3(7, 12, BATCH), dim3(32, 8)>>>(px, (float*)d_out);
    final_aux_k<<<(BATCH * CDIM + 255) / 256, 256>>>(px, (float*)d_out);
}

// round 17
// speedup vs baseline: 1.0725x; 1.0023x over previous
#include <cuda_runtime.h>
#include <cuda_fp16.h>
#include <math.h>
#include <stdint.h>

#define DEPTHN 12
#define BATCH 128
#define NTOK 197
#define NSP 196
#define CDIM 384
#define NHEAD 6
#define HDIM 64
#define MROWS (BATCH*NTOK)      /* 25216 */
#define FFDIM 1536
#define QKVDIM 1152
#define NKG 13                  /* attention k/n groups: 13*16 = 208 >= 197 */

/* per-layer packed half-weight layout */
#define W_QKV_OFF 0
#define W_PROJ_OFF 442368
#define W_FC1_OFF 589824
#define W_FC2_OFF 1179648
#define LW 1769472

/* ---------------- scratch (device globals; zero-initialized) ------------- */
__device__ float  g_x   [MROWS*CDIM];
__device__ __half g_h16 [MROWS*CDIM];
__device__ __half g_qkv16[MROWS*QKVDIM];
__device__ __half g_ao16[MROWS*CDIM];
__device__ __half g_ffn16[(long long)MROWS*FFDIM];
__device__ __half g_wh  [(long long)DEPTHN*LW];
__device__ float  g_pol [BATCH*NTOK];
__device__ float  g_ph  [BATCH*NSP*NHEAD*HDIM];
__device__ float  g_glob[BATCH*NHEAD*32];
__device__ float  g_den [BATCH];

__device__ __forceinline__ float gelu_f(float x) {
    return 0.5f * x * (1.0f + erff(x * 0.70710678118654752440f));
}

__device__ __forceinline__ uint32_t smem_u32(const void* p) {
    uint32_t a;
    asm("{ .reg .u64 t; cvta.to.shared.u64 t, %1; cvt.u32.u64 %0, t; }" : "=r"(a) : "l"(p));
    return a;
}

__device__ __forceinline__ uint32_t pack_h2(float lo, float hi) {
    uint32_t r;
    asm("cvt.rn.f16x2.f32 %0, %1, %2;" : "=r"(r) : "f"(hi), "f"(lo));
    return r;
}

__device__ __forceinline__ void cp_async16(uint32_t saddr, const void* g) {
    asm volatile("cp.async.cg.shared.global [%0], [%1], 16;" :: "r"(saddr), "l"(g));
}
#define CP_COMMIT() asm volatile("cp.async.commit_group;" ::: "memory")
#define CP_WAIT(n)  asm volatile("cp.async.wait_group %0;" :: "n"(n) : "memory")

__device__ __forceinline__ void ldsm_x4(uint32_t& r0, uint32_t& r1,
                                        uint32_t& r2, uint32_t& r3, uint32_t a) {
    asm volatile("ldmatrix.sync.aligned.m8n8.x4.shared.b16 {%0,%1,%2,%3}, [%4];"
                 : "=r"(r0), "=r"(r1), "=r"(r2), "=r"(r3) : "r"(a));
}
__device__ __forceinline__ void ldsm_x2(uint32_t& r0, uint32_t& r1, uint32_t a) {
    asm volatile("ldmatrix.sync.aligned.m8n8.x2.shared.b16 {%0,%1}, [%2];"
                 : "=r"(r0), "=r"(r1) : "r"(a));
}

__device__ __forceinline__ void mma_f16(
    float& d0, float& d1, float& d2, float& d3,
    uint32_t a0, uint32_t a1, uint32_t a2, uint32_t a3,
    uint32_t b0, uint32_t b1)
{
    asm volatile(
        "mma.sync.aligned.m16n8k16.row.col.f32.f16.f16.f32 "
        "{%0,%1,%2,%3}, {%4,%5,%6,%7}, {%8,%9}, {%0,%1,%2,%3};"
        : "+f"(d0), "+f"(d1), "+f"(d2), "+f"(d3)
        : "r"(a0), "r"(a1), "r"(a2), "r"(a3), "r"(b0), "r"(b1));
}

/* ---------------- weights fp32 -> fp16, all 4 segments in one launch ----- */
__global__ void cvtw_all_k(const float* __restrict__ qkv_w,
                           const float* __restrict__ proj_w,
                           const float* __restrict__ fc1_w,
                           const float* __restrict__ fc2_w,
                           __half* __restrict__ dstbase)
{
    const int l = blockIdx.z >> 2, seg = blockIdx.z & 3;
    const float* src;
    int perL, off;
    switch (seg) {
        case 0:  src = qkv_w;  perL = QKVDIM * CDIM; off = W_QKV_OFF;  break;
        case 1:  src = proj_w; perL = CDIM * CDIM;   off = W_PROJ_OFF; break;
        case 2:  src = fc1_w;  perL = FFDIM * CDIM;  off = W_FC1_OFF;  break;
        default: src = fc2_w;  perL = CDIM * FFDIM;  off = W_FC2_OFF;  break;
    }
    long long i = ((long long)blockIdx.x * blockDim.x + threadIdx.x) * 2;
    if (i < perL) {
        float2 v = *(const float2*)(src + (long long)l * perL + i);
        *(__half2*)(dstbase + (long long)l * LW + off + i) = __floats2half2_rn(v.x, v.y);
    }
}

/* ================= dense fp16 HMMA GEMM (R8/R14 best config) =============
 * C[m,n] = sum_k A[m,k]*B[n,k] + bias[n]   (EPI: 0 none, 1 gelu, 2 +R)
 * 256 threads, 8 warps (2M x 4N), warp 64x32; ldmatrix; 2-stage cp.async.
 */
#define DENSE_SMEM 73728

template<int EPI, bool OUTH>
__global__ void __launch_bounds__(256, 2)
hgemm_k(const __half* __restrict__ A, const __half* __restrict__ B,
        const float* __restrict__ bias, const float* __restrict__ R,
        void* __restrict__ Cv, int K, int lda, int ldb, int ldc)
{
    extern __shared__ __half hsm[];
    __half* As = hsm;              /* [2][128*72] */
    __half* Bs = hsm + 18432;
    const uint32_t asb = smem_u32(As), bsb = smem_u32(Bs);

    const int tid = threadIdx.x, wid = tid >> 5, lane = tid & 31;
    const int lane4 = lane >> 2, lanek = lane & 3;
    const int warpM = wid & 1, warpN = wid >> 1;
    const int m0 = blockIdx.y * 128, n0 = blockIdx.x * 128;

    const int mat = lane >> 3;
    const int arow = (lane & 7) + (mat & 1) * 8;
    const int acol = (mat >> 1) * 8;
    const int brow = lane & 7;
    const int bcol = ((lane >> 3) & 1) * 8;

    float acc[4][4][4];
    #pragma unroll
    for (int i = 0; i < 4; i++)
        #pragma unroll
        for (int j = 0; j < 4; j++)
            #pragma unroll
            for (int r = 0; r < 4; r++) acc[i][j][r] = 0.f;

#define HISSUE(t_, s_) do {                                                     \
    int k0_ = (t_) * 64;                                                        \
    _Pragma("unroll")                                                           \
    for (int i_ = 0; i_ < 4; i_++) {                                            \
        int idx_ = tid + 256 * i_;                                              \
        int row_ = idx_ >> 3, ch_ = idx_ & 7;                                   \
        uint32_t so_ = (uint32_t)(((s_) * 9216 + row_ * 72 + ch_ * 8) * 2);     \
        cp_async16(asb + so_, A + (size_t)(m0 + row_) * lda + k0_ + ch_ * 8);   \
        cp_async16(bsb + so_, B + (size_t)(n0 + row_) * ldb + k0_ + ch_ * 8);   \
    }                                                                           \
    CP_COMMIT();                                                                \
} while (0)

    const int T = K >> 6;
    HISSUE(0, 0);

    for (int t = 0; t < T; t++) {
        int p = t & 1;
        if (t + 1 < T) { HISSUE(t + 1, p ^ 1); CP_WAIT(1); }
        else           { CP_WAIT(0); }
        __syncthreads();

        uint32_t aAddr[4], bAddr[4];
        #pragma unroll
        for (int mf = 0; mf < 4; mf++)
            aAddr[mf] = asb + (uint32_t)((p * 9216 + (warpM * 64 + mf * 16 + arow) * 72 + acol) * 2);
        #pragma unroll
        for (int nf = 0; nf < 4; nf++)
            bAddr[nf] = bsb + (uint32_t)((p * 9216 + (warpN * 32 + nf * 8 + brow) * 72 + bcol) * 2);

        #pragma unroll
        for (int ks = 0; ks < 4; ks++) {
            uint32_t a[4][4], b[4][2];
            #pragma unroll
            for (int mf = 0; mf < 4; mf++)
                ldsm_x4(a[mf][0], a[mf][1], a[mf][2], a[mf][3], aAddr[mf] + ks * 32);
            #pragma unroll
            for (int nf = 0; nf < 4; nf++)
                ldsm_x2(b[nf][0], b[nf][1], bAddr[nf] + ks * 32);
            #pragma unroll
            for (int mf = 0; mf < 4; mf++)
                #pragma unroll
                for (int nf = 0; nf < 4; nf++)
                    mma_f16(acc[mf][nf][0], acc[mf][nf][1],
                            acc[mf][nf][2], acc[mf][nf][3],
                            a[mf][0], a[mf][1], a[mf][2], a[mf][3],
                            b[nf][0], b[nf][1]);
        }
        if (t + 1 < T) __syncthreads();
    }
#undef HISSUE

    /* epilogue */
    #pragma unroll
    for (int mf = 0; mf < 4; mf++) {
        int m = m0 + warpM * 64 + mf * 16 + lane4;
        #pragma unroll
        for (int nf = 0; nf < 4; nf++) {
            int n = n0 + warpN * 32 + nf * 8 + lanek * 2;
            float bz0 = bias ? __ldg(bias + n)     : 0.f;
            float bz1 = bias ? __ldg(bias + n + 1) : 0.f;
            size_t gi0 = (size_t)m * ldc + n;
            size_t gi1 = (size_t)(m + 8) * ldc + n;
            float v0 = acc[mf][nf][0] + bz0;
            float v1 = acc[mf][nf][1] + bz1;
            float v2 = acc[mf][nf][2] + bz0;
            float v3 = acc[mf][nf][3] + bz1;
            if (EPI == 1) {
                v0 = gelu_f(v0); v1 = gelu_f(v1);
                v2 = gelu_f(v2); v3 = gelu_f(v3);
            } else if (EPI == 2) {
                v0 += R[gi0]; v1 += R[gi0 + 1];
                v2 += R[gi1]; v3 += R[gi1 + 1];
            }
            if (OUTH) {
                __half* C = (__half*)Cv;
                *(__half2*)(C + gi0) = __floats2half2_rn(v0, v1);
                *(__half2*)(C + gi1) = __floats2half2_rn(v2, v3);
            } else {
                float* C = (float*)Cv;
                *(float2*)(C + gi0) = make_float2(v0, v1);
                *(float2*)(C + gi1) = make_float2(v2, v3);
            }
        }
    }
}

/* ================= fused attention: S=QK^T -> softmax -> O=P@V ===========
 * 13 k/n groups (208 cols >= 197) instead of 16 -> 19% fewer MMAs; removed
 * work was exact zeros (bit-identical result).
 */
#define FUSED_SMEM 90112

__global__ void __launch_bounds__(256)
attn_fused_k(const __half* __restrict__ qkv, const float* __restrict__ pol,
             __half* __restrict__ ao)
{
    extern __shared__ __half ssm[];
    __half* Qs = ssm;                       /* [128][72]  */
    __half* Ks = ssm + 9216;                /* [256][72]  */
    __half* Vs = ssm + 27648;               /* [64][264]  */
    float* pol_s = (float*)(ssm + 44544);

    const int tid = threadIdx.x, wid = tid >> 5, lane = tid & 31;
    const int bh = blockIdx.y, b = bh / NHEAD, h = bh % NHEAD;
    const int m0 = blockIdx.x * 128;

    const int mat = lane >> 3;
    const int arow = (lane & 7) + (mat & 1) * 8;
    const int acol = (mat >> 1) * 8;
    const int brow = (lane & 7) + ((lane >> 4) << 3);
    const int bcol = ((lane >> 3) & 1) * 8;
    const int vrow = lane & 7;
    const int vcol = ((lane >> 3) & 1) * 8;

    const __half* qb = qkv + (size_t)b * NTOK * QKVDIM + h * HDIM;
    const __half* kb = qb + CDIM;
    const __half* vb = qb + 2 * CDIM;

    for (int i = tid; i < NTOK; i += 256) pol_s[i] = pol[b * NTOK + i];

    const uint4 zero4 = make_uint4(0, 0, 0, 0);
    #pragma unroll
    for (int p = 0; p < 2; p++) {
        int row = (tid >> 2) + p * 64;
        int col = (tid & 3) * 16;
        uint4 v0 = zero4, v1 = zero4;
        if (m0 + row < NTOK) {
            const __half* s = qb + (size_t)(m0 + row) * QKVDIM + col;
            v0 = *(const uint4*)s; v1 = *(const uint4*)(s + 8);
        }
        *(uint4*)&Qs[row * 72 + col]     = v0;
        *(uint4*)&Qs[row * 72 + col + 8] = v1;
    }
    /* K rows 0..207 (only 13 groups used) */
    #pragma unroll
    for (int p = 0; p < 4; p++) {
        int row = (tid >> 2) + p * 64;
        if (row < 208) {
            int col = (tid & 3) * 16;
            uint4 v0 = zero4, v1 = zero4;
            if (row < NTOK) {
                const __half* s = kb + (size_t)row * QKVDIM + col;
                v0 = *(const uint4*)s; v1 = *(const uint4*)(s + 8);
            }
            *(uint4*)&Ks[row * 72 + col]     = v0;
            *(uint4*)&Ks[row * 72 + col + 8] = v1;
        }
    }
    {
        int n = tid & 63, k4 = tid >> 6;
        #pragma unroll
        for (int i = 0; i < 52; i++) {          /* rows 0..207 */
            int k = k4 + 4 * i;
            __half v = (k < NTOK) ? vb[(size_t)k * QKVDIM + n] : __half(0.f);
            Vs[n * 264 + k] = v;
        }
    }
    __syncthreads();

    /* ---- S = Q @ K^T (13 n-groups = 26 n8 blocks, 208 cols) ---- */
    float acc[2 * NKG][4];
    #pragma unroll
    for (int j = 0; j < 2 * NKG; j++)
        #pragma unroll
        for (int r = 0; r < 4; r++) acc[j][r] = 0.f;

    const uint32_t qsb = smem_u32(Qs), ksb = smem_u32(Ks), vsb = smem_u32(Vs);
    const uint32_t aBase = qsb + (uint32_t)(((wid * 16 + arow) * 72 + acol) * 2);
    const uint32_t bBase = ksb + (uint32_t)((brow * 72 + bcol) * 2);

    #pragma unroll
    for (int ks = 0; ks < 4; ks++) {
        uint32_t a0, a1, a2, a3;
        ldsm_x4(a0, a1, a2, a3, aBase + ks * 32);
        #pragma unroll
        for (int ng = 0; ng < NKG; ng++) {
            uint32_t b0, b1, b2, b3;
            ldsm_x4(b0, b1, b2, b3, bBase + (uint32_t)(ng * 16 * 72 * 2) + ks * 32);
            mma_f16(acc[ng*2][0], acc[ng*2][1], acc[ng*2][2], acc[ng*2][3],
                    a0, a1, a2, a3, b0, b1);
            mma_f16(acc[ng*2+1][0], acc[ng*2+1][1], acc[ng*2+1][2], acc[ng*2+1][3],
                    a0, a1, a2, a3, b2, b3);
        }
    }

    /* ---- in-register policy softmax ---- */
    const int rr = lane >> 2, t = lane & 3;
    const int gm1 = m0 + wid * 16 + rr;
    const int gm2 = gm1 + 8;

    #pragma unroll
    for (int j = 0; j < 2 * NKG; j++) {
        acc[j][0] *= 0.125f; acc[j][1] *= 0.125f;
        acc[j][2] *= 0.125f; acc[j][3] *= 0.125f;
    }

    float mx1 = -1e30f, mx2 = -1e30f;
    #pragma unroll
    for (int j = 0; j < 2 * NKG; j++) {
        int col = j * 8 + t * 2;
        if (col < NTOK)     { mx1 = fmaxf(mx1, acc[j][0]); mx2 = fmaxf(mx2, acc[j][2]); }
        if (col + 1 < NTOK) { mx1 = fmaxf(mx1, acc[j][1]); mx2 = fmaxf(mx2, acc[j][3]); }
    }
    mx1 = fmaxf(mx1, __shfl_xor_sync(0xffffffffu, mx1, 1));
    mx1 = fmaxf(mx1, __shfl_xor_sync(0xffffffffu, mx1, 2));
    mx2 = fmaxf(mx2, __shfl_xor_sync(0xffffffffu, mx2, 1));
    mx2 = fmaxf(mx2, __shfl_xor_sync(0xffffffffu, mx2, 2));

    float sum1 = 0.f, sum2 = 0.f;
    #pragma unroll
    for (int j = 0; j < 2 * NKG; j++) {
        int col = j * 8 + t * 2;
        if (col < NTOK) {
            float ap = pol_s[col];
            float a1v = (col == gm1) ? 1.0f : ap;
            float a2v = (col == gm2) ? 1.0f : ap;
            float e1 = __expf(acc[j][0] - mx1) * a1v; acc[j][0] = e1; sum1 += e1;
            float e2 = __expf(acc[j][2] - mx2) * a2v; acc[j][2] = e2; sum2 += e2;
        } else { acc[j][0] = 0.f; acc[j][2] = 0.f; }
        if (col + 1 < NTOK) {
            float ap = pol_s[col + 1];
            float a1v = (col + 1 == gm1) ? 1.0f : ap;
            float a2v = (col + 1 == gm2) ? 1.0f : ap;
            float e1 = __expf(acc[j][1] - mx1) * a1v; acc[j][1] = e1; sum1 += e1;
            float e2 = __expf(acc[j][3] - mx2) * a2v; acc[j][3] = e2; sum2 += e2;
        } else { acc[j][1] = 0.f; acc[j][3] = 0.f; }
    }
    sum1 += __shfl_xor_sync(0xffffffffu, sum1, 1);
    sum1 += __shfl_xor_sync(0xffffffffu, sum1, 2);
    sum2 += __shfl_xor_sync(0xffffffffu, sum2, 1);
    sum2 += __shfl_xor_sync(0xffffffffu, sum2, 2);
    float inv1 = 1.0f / sum1, inv2 = 1.0f / sum2;

    /* ---- pack P: C-fragment layout -> A-fragments ---- */
    uint32_t pa[NKG][4];
    #pragma unroll
    for (int g = 0; g < NKG; g++) {
        pa[g][0] = pack_h2(acc[2*g][0]   * inv1, acc[2*g][1]   * inv1);
        pa[g][1] = pack_h2(acc[2*g][2]   * inv2, acc[2*g][3]   * inv2);
        pa[g][2] = pack_h2(acc[2*g+1][0] * inv1, acc[2*g+1][1] * inv1);
        pa[g][3] = pack_h2(acc[2*g+1][2] * inv2, acc[2*g+1][3] * inv2);
    }

    /* ---- O = P @ V (13 k-groups) ---- */
    float oacc[8][4];
    #pragma unroll
    for (int nf = 0; nf < 8; nf++)
        #pragma unroll
        for (int r = 0; r < 4; r++) oacc[nf][r] = 0.f;

    uint32_t vAddr[8];
    #pragma unroll
    for (int nf = 0; nf < 8; nf++)
        vAddr[nf] = vsb + (uint32_t)(((nf * 8 + vrow) * 264 + vcol) * 2);

    #pragma unroll
    for (int g = 0; g < NKG; g++) {
        #pragma unroll
        for (int nf = 0; nf < 8; nf++) {
            uint32_t b0, b1;
            ldsm_x2(b0, b1, vAddr[nf] + g * 32);
            mma_f16(oacc[nf][0], oacc[nf][1], oacc[nf][2], oacc[nf][3],
                    pa[g][0], pa[g][1], pa[g][2], pa[g][3], b0, b1);
        }
    }

    /* ---- write O ---- */
    #pragma unroll
    for (int nf = 0; nf < 8; nf++) {
        int n = nf * 8 + t * 2;
        if (gm1 < NTOK)
            *(__half2*)(ao + (size_t)(b * NTOK + gm1) * CDIM + h * HDIM + n) =
                __floats2half2_rn(oacc[nf][0], oacc[nf][1]);
        if (gm2 < NTOK)
            *(__half2*)(ao + (size_t)(b * NTOK + gm2) * CDIM + h * HDIM + n) =
                __floats2half2_rn(oacc[nf][2], oacc[nf][3]);
    }
}

/* ---------------- block reductions --------------------------------------- */
__device__ __forceinline__ float blockReduceSum(float v, float* sh) {
    int tid = threadIdx.x, lane = tid & 31, w = tid >> 5;
    #pragma unroll
    for (int o = 16; o; o >>= 1) v += __shfl_xor_sync(0xffffffffu, v, o);
    if (lane == 0) sh[w] = v;
    __syncthreads();
    int nw = (blockDim.x + 31) >> 5;
    v = (tid < nw) ? sh[tid] : 0.f;
    if (w == 0) {
        #pragma unroll
        for (int o = 16; o; o >>= 1) v += __shfl_xor_sync(0xffffffffu, v, o);
        if (lane == 0) sh[0] = v;
    }
    __syncthreads();
    float r = sh[0];
    __syncthreads();
    return r;
}

/* ---------------- LayerNorm: warp-per-row, float4 I/O -------------------- */
__global__ void __launch_bounds__(256)
ln_k(const float* __restrict__ x, const float* __restrict__ w,
     const float* __restrict__ bb, __half* __restrict__ out, float eps)
{
    const int wid = threadIdx.x >> 5, lane = threadIdx.x & 31;
    const long long row = (long long)blockIdx.x * 8 + wid;
    const float4* xr = (const float4*)(x + row * CDIM);

    float4 v0 = xr[lane], v1 = xr[lane + 32], v2 = xr[lane + 64];
    float s = v0.x + v0.y + v0.z + v0.w
            + v1.x + v1.y + v1.z + v1.w
            + v2.x + v2.y + v2.z + v2.w;
    #pragma unroll
    for (int o = 16; o; o >>= 1) s += __shfl_xor_sync(0xffffffffu, s, o);
    float m = s * (1.f / 384.f);

    float q = (v0.x-m)*(v0.x-m) + (v0.y-m)*(v0.y-m) + (v0.z-m)*(v0.z-m) + (v0.w-m)*(v0.w-m)
            + (v1.x-m)*(v1.x-m) + (v1.y-m)*(v1.y-m) + (v1.z-m)*(v1.z-m) + (v1.w-m)*(v1.w-m)
            + (v2.x-m)*(v2.x-m) + (v2.y-m)*(v2.y-m) + (v2.z-m)*(v2.z-m) + (v2.w-m)*(v2.w-m);
    #pragma unroll
    for (int o = 16; o; o >>= 1) q += __shfl_xor_sync(0xffffffffu, q, o);
    float rs = rsqrtf(q * (1.f / 384.f) + eps);

    const float4* wv = (const float4*)w;
    const float4* bv = (const float4*)bb;
    __half* orow = out + row * CDIM;

    #pragma unroll
    for (int p = 0; p < 3; p++) {
        float4 vv = (p == 0) ? v0 : (p == 1) ? v1 : v2;
        float4 ww = wv[lane + p * 32];
        float4 bbv = bv[lane + p * 32];
        uint32_t lo = pack_h2((vv.x - m) * rs * ww.x + bbv.x,
                              (vv.y - m) * rs * ww.y + bbv.y);
        uint32_t hi = pack_h2((vv.z - m) * rs * ww.z + bbv.z,
                              (vv.w - m) * rs * ww.w + bbv.w);
        uint2 o2 = make_uint2(lo, hi);
        *(uint2*)(orow + (lane + p * 32) * 4) = o2;
    }
}

/* ---------------- tiled transpose init / final --------------------------- */
__global__ void init_tp_k(const float* __restrict__ xin, float* __restrict__ x)
{
    __shared__ float t[32][33];
    int b = blockIdx.z;
    int hw0 = blockIdx.x * 32, c0 = blockIdx.y * 32;
    int tx = threadIdx.x, ty = threadIdx.y;
    #pragma unroll
    for (int i = 0; i < 32; i += 8) {
        int c = c0 + ty + i, hw = hw0 + tx;
        if (hw < NSP)
            t[ty + i][tx] = xin[((size_t)b * CDIM + c) * NSP + hw];
    }
    __syncthreads();
    #pragma unroll
    for (int i = 0; i < 32; i += 8) {
        int hw = hw0 + ty + i, c = c0 + tx;
        if (hw < NSP)
            x[((size_t)b * NTOK + 1 + hw) * CDIM + c] = t[tx][ty + i];
    }
}

__global__ void init_aux_k(const float* __restrict__ cls, const float* __restrict__ polin,
                           float* __restrict__ x, float* __restrict__ pol)
{
    int idx = blockIdx.x * blockDim.x + threadIdx.x;
    if (idx < BATCH * CDIM) {
        int b = idx / CDIM, c = idx % CDIM;
        x[(size_t)b * NTOK * CDIM + c] = cls[idx];
    }
    if (idx < BATCH * NTOK) pol[idx] = polin[idx];
}

__global__ void final_tp_k(const float* __restrict__ x, float* __restrict__ out)
{
    __shared__ float t[32][33];
    int b = blockIdx.z;
    int hw0 = blockIdx.x * 32, c0 = blockIdx.y * 32;
    int tx = threadIdx.x, ty = threadIdx.y;
    #pragma unroll
    for (int i = 0; i < 32; i += 8) {
        int hw = hw0 + ty + i, c = c0 + tx;
        if (hw < NSP)
            t[ty + i][tx] = x[((size_t)b * NTOK + 1 + hw) * CDIM + c];
    }
    __syncthreads();
    #pragma unroll
    for (int i = 0; i < 32; i += 8) {
        int c = c0 + ty + i, hw = hw0 + tx;
        if (hw < NSP)
            out[((size_t)b * CDIM + c) * NSP + hw] = t[tx][ty + i];
    }
}

__global__ void final_aux_k(const float* __restrict__ x, float* __restrict__ out)
{
    int idx = blockIdx.x * blockDim.x + threadIdx.x;
    if (idx < BATCH * CDIM) {
        int b = idx / CDIM, c = idx % CDIM;
        out[(size_t)BATCH * CDIM * NSP + idx] = x[(size_t)b * NTOK * CDIM + c];
    }
}

/* ---------------- predictor --------------------------------------------- */
__global__ void den_k(const float* __restrict__ pol, float* __restrict__ den)
{
    __shared__ float sh[32];
    int b = blockIdx.x;
    int tid = threadIdx.x;
    float v = (tid < NSP) ? pol[b * NTOK + 1 + tid] : 0.f;
    float s = blockReduceSum(v, sh);
    if (tid == 0) den[b] = s;
}

__global__ void p1_k(const float* __restrict__ x,
                     const float* __restrict__ lnw, const float* __restrict__ lnb,
                     const float* __restrict__ Win, const float* __restrict__ bin,
                     float* __restrict__ ph)
{
    int bn = blockIdx.x;
    int b = bn / NSP, n = bn % NSP;
    int wid = threadIdx.x >> 5, lane = threadIdx.x & 31;
    __shared__ float sh[NHEAD][HDIM];

    const float* xr = x + ((long long)(b * NTOK + 1 + n)) * CDIM + wid * HDIM;
    float v0 = xr[lane], v1 = xr[lane + 32];
    float s = v0 + v1;
    #pragma unroll
    for (int o = 16; o; o >>= 1) s += __shfl_xor_sync(0xffffffffu, s, o);
    float m = s * (1.f / 64.f);
    float d0 = v0 - m, d1 = v1 - m;
    float q = d0*d0 + d1*d1;
    #pragma unroll
    for (int o = 16; o; o >>= 1) q += __shfl_xor_sync(0xffffffffu, q, o);
    float rs = rsqrtf(q * (1.f / 64.f) + 1e-5f);
    sh[wid][lane]      = d0 * rs * lnw[lane]      + lnb[lane];
    sh[wid][lane + 32] = d1 * rs * lnw[lane + 32] + lnb[lane + 32];
    __syncwarp();

    float a0 = bin[lane], a1 = bin[lane + 32];
    const float* w0 = Win + lane * 64;
    const float* w1 = Win + (lane + 32) * 64;
    #pragma unroll 8
    for (int e = 0; e < 64; e++) {
        float he = sh[wid][e];
        a0 += w0[e] * he;
        a1 += w1[e] * he;
    }
    float* o = ph + ((long long)bn * NHEAD + wid) * HDIM;
    o[lane]      = gelu_f(a0);
    o[lane + 32] = gelu_f(a1);
}

__global__ void p2_k(const float* __restrict__ ph, const float* __restrict__ pol,
                     const float* __restrict__ den, float* __restrict__ glob)
{
    int bh = blockIdx.x;
    int b = bh / NHEAD, h = bh % NHEAD;
    int tid = threadIdx.x;
    int d = tid & 31, seg = tid >> 5;
    float s = 0.f;
    for (int n = seg; n < NSP; n += 8)
        s += ph[(((long long)(b * NSP + n)) * NHEAD + h) * HDIM + 32 + d]
             * pol[b * NTOK + 1 + n];
    __shared__ float sh[8][32];
    sh[seg][d] = s;
    __syncthreads();
    if (seg == 0) {
        float t = 0.f;
        #pragma unroll
        for (int k = 0; k < 8; k++) t += sh[k][d];
        glob[(b * NHEAD + h) * 32 + d] = t / den[b];
    }
}

__global__ void p3_k(const float* __restrict__ ph, const float* __restrict__ glob,
                     const float* __restrict__ W1, const float* __restrict__ b1,
                     const float* __restrict__ W2, const float* __restrict__ b2,
                     const float* __restrict__ W3, const float* __restrict__ b3,
                     const float* __restrict__ gum, float* __restrict__ pol)
{
    int bn = blockIdx.x;
    int b = bn / NSP, n = bn % NSP;
    int wid = threadIdx.x >> 5, lane = threadIdx.x & 31;
    __shared__ float h2[NHEAD][64];
    __shared__ float o1[NHEAD][32];
    __shared__ float o2[NHEAD][16];
    __shared__ float zz[NHEAD][2];

    const float* hin = ph + ((long long)bn * NHEAD + wid) * HDIM;
    h2[wid][lane]      = hin[lane];
    h2[wid][32 + lane] = glob[(b * NHEAD + wid) * 32 + lane];
    __syncwarp();
    {
        float a = b1[lane];
        const float* wr = W1 + lane * 64;
        #pragma unroll 8
        for (int e = 0; e < 64; e++) a += wr[e] * h2[wid][e];
        o1[wid][lane] = gelu_f(a);
    }
    __syncwarp();
    if (lane < 16) {
        float a = b2[lane];
        const float* wr = W2 + lane * 32;
        #pragma unroll 8
        for (int e = 0; e < 32; e++) a += wr[e] * o1[wid][e];
        o2[wid][lane] = gelu_f(a);
    }
    __syncwarp();
    if (lane < 2) {
        float a = b3[lane];
        const float* wr = W3 + lane * 16;
        #pragma unroll
        for (int e = 0; e < 16; e++) a += wr[e] * o2[wid][e];
        zz[wid][lane] = a;
    }
    __syncthreads();
    if (threadIdx.x == 0) {
        float s0 = 0.f, s1 = 0.f;
        #pragma unroll
        for (int h = 0; h < NHEAD; h++) {
            float z0 = zz[h][0], z1 = zz[h][1];
            float mx = fmaxf(z0, z1);
            float lse = mx + logf(expf(z0 - mx) + expf(z1 - mx));
            s0 += z0 - lse;
            s1 += z1 - lse;
        }
        s0 *= (1.f / 6.f); s1 *= (1.f / 6.f);
        float u0 = gum[((long long)b * NSP + n) * 2 + 0];
        float u1 = gum[((long long)b * NSP + n) * 2 + 1];
        float g0 = -logf(-logf(u0 + 1e-10f) + 1e-10f);
        float g1 = -logf(-logf(u1 + 1e-10f) + 1e-10f);
        int idx = b * NTOK + 1 + n;
        float keep = (s0 + g0 >= s1 + g1) ? pol[idx] : 0.f;
        pol[idx] = keep;
    }
}

/* ---------------- host-side ------------------------------------------------ */
extern "C" void kernel_launch(void* const* d_in, const int* in_sizes, int n_in,
                              void* d_out, int out_size)
{
    const float* in_x     = (const float*)d_in[0];
    const float* in_cls   = (const float*)d_in[1];
    const float* in_pol   = (const float*)d_in[2];
    const float* in_gum   = (const float*)d_in[3];
    const float* ln1_w    = (const float*)d_in[4];
    const float* ln1_b    = (const float*)d_in[5];
    const float* qkv_w    = (const float*)d_in[6];
    const float* qkv_b    = (const float*)d_in[7];
    const float* proj_w   = (const float*)d_in[8];
    const float* proj_b   = (const float*)d_in[9];
    const float* ln2_w    = (const float*)d_in[10];
    const float* ln2_b    = (const float*)d_in[11];
    const float* fc1_w    = (const float*)d_in[12];
    const float* fc1_b    = (const float*)d_in[13];
    const float* fc2_w    = (const float*)d_in[14];
    const float* fc2_b    = (const float*)d_in[15];
    const float* p_ln_w   = (const float*)d_in[16];
    const float* p_ln_b   = (const float*)d_in[17];
    const float* p_in_w   = (const float*)d_in[18];
    const float* p_in_b   = (const float*)d_in[19];
    const float* p_o1_w   = (const float*)d_in[20];
    const float* p_o1_b   = (const float*)d_in[21];
    const float* p_o2_w   = (const float*)d_in[22];
    const float* p_o2_b   = (const float*)d_in[23];
    const float* p_o3_w   = (const float*)d_in[24];
    const float* p_o3_b   = (const float*)d_in[25];

    cudaFuncSetAttribute(hgemm_k<0, true >, cudaFuncAttributeMaxDynamicSharedMemorySize, DENSE_SMEM);
    cudaFuncSetAttribute(hgemm_k<1, true >, cudaFuncAttributeMaxDynamicSharedMemorySize, DENSE_SMEM);
    cudaFuncSetAttribute(hgemm_k<2, false>, cudaFuncAttributeMaxDynamicSharedMemorySize, DENSE_SMEM);
    cudaFuncSetAttribute(attn_fused_k,      cudaFuncAttributeMaxDynamicSharedMemorySize, FUSED_SMEM);

    float  *px, *ppol, *pph, *pglob, *pden;
    __half *ph16, *pqkv16, *pao16, *pffn16, *pwh;
    cudaGetSymbolAddress((void**)&px,     g_x);
    cudaGetSymbolAddress((void**)&ph16,   g_h16);
    cudaGetSymbolAddress((void**)&pqkv16, g_qkv16);
    cudaGetSymbolAddress((void**)&pao16,  g_ao16);
    cudaGetSymbolAddress((void**)&pffn16, g_ffn16);
    cudaGetSymbolAddress((void**)&pwh,    g_wh);
    cudaGetSymbolAddress((void**)&ppol,   g_pol);
    cudaGetSymbolAddress((void**)&pph,    g_ph);
    cudaGetSymbolAddress((void**)&pglob,  g_glob);
    cudaGetSymbolAddress((void**)&pden,   g_den);

    /* weights fp32 -> fp16 scratch (single launch, all segments) */
    cvtw_all_k<<<dim3((FFDIM * CDIM / 2 + 255) / 256, 1, DEPTHN * 4), 256>>>(
        qkv_w, proj_w, fc1_w, fc2_w, pwh);

    /* init: tiled transpose + cls/policy */
    init_tp_k<<<dim3(7, 12, BATCH), dim3(32, 8)>>>(in_x, px);
    init_aux_k<<<(BATCH * CDIM + 255) / 256, 256>>>(in_cls, in_pol, px, ppol);

    int pc = 0;
    for (int i = 0; i < DEPTHN; i++) {
        const __half* wl = pwh + (long long)i * LW;
        if (i == 3 || i == 6 || i == 9) {
            den_k<<<BATCH, 256>>>(ppol, pden);
            p1_k<<<BATCH * NSP, 192>>>(px,
                p_ln_w + pc * HDIM, p_ln_b + pc * HDIM,
                p_in_w + pc * HDIM * HDIM, p_in_b + pc * HDIM, pph);
            p2_k<<<BATCH * NHEAD, 256>>>(pph, ppol, pden, pglob);
            p3_k<<<BATCH * NSP, 192>>>(pph, pglob,
                p_o1_w + pc * 32 * 64, p_o1_b + pc * 32,
                p_o2_w + pc * 16 * 32, p_o2_b + pc * 16,
                p_o3_w + pc * 2 * 16,  p_o3_b + pc * 2,
                in_gum + (long long)pc * BATCH * NSP * 2, ppol);
            pc++;
        }

        ln_k<<<MROWS / 8, 256>>>(px, ln1_w + i * CDIM, ln1_b + i * CDIM, ph16, 1e-6f);

        hgemm_k<0, true><<<dim3(QKVDIM / 128, MROWS / 128), 256, DENSE_SMEM>>>(
            ph16, wl + W_QKV_OFF, qkv_b + i * QKVDIM, nullptr, pqkv16,
            CDIM, CDIM, CDIM, QKVDIM);

        attn_fused_k<<<dim3(2, BATCH * NHEAD), 256, FUSED_SMEM>>>(pqkv16, ppol, pao16);

        hgemm_k<2, false><<<dim3(CDIM / 128, MROWS / 128), 256, DENSE_SMEM>>>(
            pao16, wl + W_PROJ_OFF, proj_b + i * CDIM, px, px,
            CDIM, CDIM, CDIM, CDIM);

        ln_k<<<MROWS / 8, 256>>>(px, ln2_w + i * CDIM, ln2_b + i * CDIM, ph16, 1e-6f);

        hgemm_k<1, true><<<dim3(FFDIM / 128, MROWS / 128), 256, DENSE_SMEM>>>(
            ph16, wl + W_FC1_OFF, fc1_b + i * FFDIM, nullptr, pffn16,
            CDIM, CDIM, CDIM, FFDIM);

        hgemm_k<2, false><<<dim3(CDIM / 128, MROWS / 128), 256, DENSE_SMEM>>>(
            pffn16, wl + W_FC2_OFF, fc2_b + i * CDIM, px, px,
            FFDIM, FFDIM, FFDIM, CDIM);
    }

    /* final: tiled transpose + cls tail */
    final_tp_k<<<dim3(7, 12, BATCH), dim3(32, 8)>>>(px, (float*)d_out);
    final_aux_k<<<(BATCH * CDIM + 255) / 256, 256>>>(px, (float*)d_out);
}